// round 10
// baseline (speedup 1.0000x reference)
#include <cuda_runtime.h>
#include <cuda_fp16.h>
#include <cstdint>
#include <stdint.h>
#include <math.h>

// ---------------- problem constants ----------------
constexpr int Nb = 2;
constexpr int Cc = 256;
constexpr int Ss = 4096;
constexpr int Hh = 4;
constexpr int Dh = 64;
constexpr int NH = Nb * Hh;
constexpr float EPSV = 1e-5f;
constexpr float QSCALE = (1.0f / 64.0f) * 1.4426950408889634f;  // folded into WQ
constexpr int QSPLIT = 4;
constexpr int KSPLIT = 4;

// ---------------- device scratch ----------------
__device__ float  g_r    [Nb * Ss * Cc];
__device__ __half g_normh[Nb * Ss * Cc];
__device__ __half g_Qh   [NH * Ss * Dh];
__device__ __half g_Kh   [NH * Ss * Dh];
__device__ __half g_Vh   [NH * Ss * Dh];   // post-stats: scaled by inv_k
__device__ float  g_stp  [QSPLIT * NH * Ss];
__device__ float  g_po   [KSPLIT * NH * Ss * Dh];
__device__ float  g_attn [Nb * Ss * Cc];
__device__ __half g_uh   [Nb * Ss * Cc];
__device__ __half g_h1h  [Nb * Ss * Cc];
__device__ __half g_W1h  [Cc * Cc];
__device__ __half g_W2h  [Cc * Cc];
__device__ __half g_WQh  [Hh * Cc * Dh];   // pre-scaled by QSCALE
__device__ __half g_WKh  [Hh * Cc * Dh];
__device__ __half g_WVh  [Hh * Cc * Dh];
__device__ float  g_o    [Nb * Ss * Cc];

// ---------------- helpers ----------------
__device__ __forceinline__ unsigned smem_u32(const void* p) {
    return (unsigned)__cvta_generic_to_shared(p);
}
__device__ __forceinline__ void ldmx4(unsigned* r, unsigned a) {
    asm volatile("ldmatrix.sync.aligned.m8n8.x4.shared.b16 {%0,%1,%2,%3},[%4];"
                 : "=r"(r[0]), "=r"(r[1]), "=r"(r[2]), "=r"(r[3]) : "r"(a));
}
__device__ __forceinline__ void ldmx4t(unsigned* r, unsigned a) {
    asm volatile("ldmatrix.sync.aligned.m8n8.x4.trans.shared.b16 {%0,%1,%2,%3},[%4];"
                 : "=r"(r[0]), "=r"(r[1]), "=r"(r[2]), "=r"(r[3]) : "r"(a));
}
__device__ __forceinline__ void mma16816(float* c, const unsigned* a, const unsigned* b) {
    asm volatile(
        "mma.sync.aligned.m16n8k16.row.col.f32.f16.f16.f32 "
        "{%0,%1,%2,%3},{%4,%5,%6,%7},{%8,%9},{%0,%1,%2,%3};"
        : "+f"(c[0]), "+f"(c[1]), "+f"(c[2]), "+f"(c[3])
        : "r"(a[0]), "r"(a[1]), "r"(a[2]), "r"(a[3]), "r"(b[0]), "r"(b[1]));
}
__device__ __forceinline__ void cpa16(unsigned dst, const void* src) {
    asm volatile("cp.async.ca.shared.global [%0], [%1], 16;" :: "r"(dst), "l"(src));
}
__device__ __forceinline__ void cpa_commit() {
    asm volatile("cp.async.commit_group;");
}
template <int N>
__device__ __forceinline__ void cpa_wait() {
    asm volatile("cp.async.wait_group %0;" :: "n"(N));
}

// ---------------- fused: transpose x[n,c,s] -> r[n,s,c] + LN1 -> normh ----------------
__global__ void k_tin_ln(const float* __restrict__ x,
                         const float* __restrict__ w, const float* __restrict__ b) {
    __shared__ float t[256][33];
    int n = blockIdx.y, s0 = blockIdx.x * 32;
    int tx = threadIdx.x, ty = threadIdx.y;
#pragma unroll
    for (int i = 0; i < 32; i++)
        t[ty + 8 * i][tx] = x[((size_t)(n * Cc + ty + 8 * i)) * Ss + s0 + tx];
    __syncthreads();
    int lane = tx;
#pragma unroll
    for (int j = 0; j < 4; j++) {
        int s = ty * 4 + j;
        float vals[8];
        float s1 = 0.f, s2 = 0.f;
#pragma unroll
        for (int u = 0; u < 8; u++) {
            float v = t[lane + 32 * u][s];
            vals[u] = v; s1 += v; s2 += v * v;
        }
#pragma unroll
        for (int o = 16; o; o >>= 1) {
            s1 += __shfl_xor_sync(0xffffffffu, s1, o);
            s2 += __shfl_xor_sync(0xffffffffu, s2, o);
        }
        float mean = s1 * (1.0f / Cc);
        float rstd = rsqrtf(s2 * (1.0f / Cc) - mean * mean + EPSV);
        size_t rowo = ((size_t)n * Ss + s0 + s) * Cc;
#pragma unroll
        for (int u = 0; u < 8; u++) {
            int c = lane + 32 * u;
            g_r[rowo + c] = vals[u];
            g_normh[rowo + c] = __float2half((vals[u] - mean) * rstd * w[c] + b[c]);
        }
    }
}

// ---------------- transpose out ----------------
__global__ void k_transpose_out(float* __restrict__ out) {
    __shared__ float t[32][33];
    int n = blockIdx.z;
    int s0 = blockIdx.x * 32, c0 = blockIdx.y * 32;
    int tx = threadIdx.x, ty = threadIdx.y;
#pragma unroll
    for (int i = 0; i < 4; i++)
        t[ty + 8 * i][tx] = g_o[((size_t)(n * Ss + s0 + ty + 8 * i)) * Cc + c0 + tx];
    __syncthreads();
#pragma unroll
    for (int i = 0; i < 4; i++)
        out[((size_t)(n * Cc + c0 + ty + 8 * i)) * Ss + s0 + tx] = t[tx][ty + 8 * i];
}

// ---------------- all weights fp32 -> fp16 once ----------------
__global__ void k_cvtw(const float* __restrict__ W1, const float* __restrict__ W2,
                       const float* __restrict__ WQ, const float* __restrict__ WK,
                       const float* __restrict__ WV) {
    int i = blockIdx.x * 256 + threadIdx.x;
    g_W1h[i] = __float2half(W1[i]);
    g_W2h[i] = __float2half(W2[i]);
    g_WQh[i] = __float2half(WQ[i] * QSCALE);
    g_WKh[i] = __float2half(WK[i]);
    g_WVh[i] = __float2half(WV[i]);
}

// ---------------- fused: O-combine + residual + LN2 -> g_attn, g_uh ----------------
__global__ void k_oln(const float* __restrict__ w, const float* __restrict__ b) {
    int row = blockIdx.x;
    int t = threadIdx.x;
    int n = row >> 12, q = row & 4095;
    int h = t >> 6, d = t & 63;
    int nh = n * 4 + h;
    float val = 0.f;
#pragma unroll
    for (int ks = 0; ks < KSPLIT; ks++)
        val += g_po[((size_t)(ks * NH + nh) * Ss + q) * Dh + d];
    size_t idx = (size_t)row * Cc + t;
    g_attn[idx] = val;
    float v = val + g_r[idx];

    float s1 = v, s2 = v * v;
#pragma unroll
    for (int o = 16; o; o >>= 1) {
        s1 += __shfl_xor_sync(0xffffffffu, s1, o);
        s2 += __shfl_xor_sync(0xffffffffu, s2, o);
    }
    __shared__ float sm1[8], sm2[8];
    __shared__ float mb, rb;
    int w8 = t >> 5, lane = t & 31;
    if (!lane) { sm1[w8] = s1; sm2[w8] = s2; }
    __syncthreads();
    if (t == 0) {
        float a = 0.f, qq = 0.f;
#pragma unroll
        for (int i = 0; i < 8; i++) { a += sm1[i]; qq += sm2[i]; }
        float mean = a * (1.0f / Cc);
        mb = mean;
        rb = rsqrtf(qq * (1.0f / Cc) - mean * mean + EPSV);
    }
    __syncthreads();
    g_uh[idx] = __float2half((v - mb) * rb * w[t] + b[t]);
}

// ---------------- QKV projection, fp16 mma, pre-converted weights ----------------
__global__ __launch_bounds__(256) void k_qkv() {
    int which = blockIdx.y >> 2;
    int h = blockIdx.y & 3;
    int n = blockIdx.z;
    int m0 = blockIdx.x * 128;
    const __half* W = (which == 0 ? g_WQh : which == 1 ? g_WKh : g_WVh) + h * Cc * Dh;
    __half* Out = (which == 0 ? g_Qh : which == 1 ? g_Kh : g_Vh) + (size_t)(n * 4 + h) * Ss * Dh;
    const __half* A = g_normh + (size_t)n * Ss * Cc;

    __shared__ __half As[128][88];
    __shared__ __half Bs[64][88];
    int tid = threadIdx.x, lane = tid & 31, wid = tid >> 5;
    int wm = (wid >> 1) * 32;
    int wn = (wid & 1) * 32;
    float acc[2][4][4] = {};

    for (int kb = 0; kb < Cc; kb += 64) {
#pragma unroll
        for (int i = 0; i < 4; i++) {
            int idx = tid + i * 256;
            int r = idx >> 3, c8 = idx & 7;
            *(float4*)&As[r][c8 * 8] = *(const float4*)(A + (size_t)(m0 + r) * Cc + kb + c8 * 8);
        }
#pragma unroll
        for (int i = 0; i < 2; i++) {
            int idx = tid + i * 256;
            int r = idx >> 3, c8 = idx & 7;
            *(float4*)&Bs[r][c8 * 8] = *(const float4*)(W + (size_t)(kb + r) * Dh + c8 * 8);
        }
        __syncthreads();
#pragma unroll
        for (int kk = 0; kk < 64; kk += 16) {
            unsigned a[2][4], b[4][2];
#pragma unroll
            for (int mi = 0; mi < 2; mi++)
                ldmx4(a[mi], smem_u32(&As[wm + mi * 16 + (lane & 15)][kk + (lane >> 4) * 8]));
#pragma unroll
            for (int p = 0; p < 2; p++) {
                unsigned r4[4];
                ldmx4t(r4, smem_u32(&Bs[kk + (lane & 7) + ((lane >> 3) & 1) * 8]
                                       [wn + p * 16 + (lane >> 4) * 8]));
                b[2 * p][0] = r4[0]; b[2 * p][1] = r4[1];
                b[2 * p + 1][0] = r4[2]; b[2 * p + 1][1] = r4[3];
            }
#pragma unroll
            for (int mi = 0; mi < 2; mi++)
#pragma unroll
                for (int nj = 0; nj < 4; nj++)
                    mma16816(acc[mi][nj], a[mi], b[nj]);
        }
        __syncthreads();
    }
#pragma unroll
    for (int mi = 0; mi < 2; mi++) {
        int r = m0 + wm + mi * 16 + (lane >> 2);
#pragma unroll
        for (int nj = 0; nj < 4; nj++) {
            int c = wn + nj * 8 + 2 * (lane & 3);
            *(__half2*)(Out + (size_t)r * Dh + c) =
                __floats2half2_rn(acc[mi][nj][0], acc[mi][nj][1]);
            *(__half2*)(Out + (size_t)(r + 8) * Dh + c) =
                __floats2half2_rn(acc[mi][nj][2], acc[mi][nj][3]);
        }
    }
}

// ---------------- pass 1: per-k partial sum of exp2(S) — round-8 config ----------------
__global__ __launch_bounds__(256) void k_stats() {
    int nh = blockIdx.y;
    int qs = blockIdx.z;
    int k0 = blockIdx.x * 128;
    const __half* Kp = g_Kh + (size_t)nh * Ss * Dh;
    const __half* Qp = g_Qh + (size_t)nh * Ss * Dh;
    constexpr int NITER = Ss / 128 / QSPLIT;   // 8
    int qbase = qs * (Ss / QSPLIT);

    __shared__ __half As[128][72];
    __shared__ __half Bs[2][128][72];
    __shared__ float sred[2][128];

    int tid = threadIdx.x, lane = tid & 31, wid = tid >> 5;
    int wm = (wid >> 1) * 32;
    int wn = (wid & 1) * 64;

#pragma unroll
    for (int i = 0; i < 4; i++) {
        int idx = tid + i * 256;
        int r = idx >> 3, c8 = idx & 7;
        *(float4*)&As[r][c8 * 8] = *(const float4*)(Kp + (size_t)(k0 + r) * Dh + c8 * 8);
    }
#pragma unroll
    for (int i = 0; i < 4; i++) {
        int idx = tid + i * 256;
        int r = idx >> 3, c8 = idx & 7;
        cpa16(smem_u32(&Bs[0][r][c8 * 8]), Qp + (size_t)(qbase + r) * Dh + c8 * 8);
    }
    cpa_commit();
    __syncthreads();

    unsigned a[2][4][4];
#pragma unroll
    for (int mi = 0; mi < 2; mi++)
#pragma unroll
        for (int t = 0; t < 4; t++)
            ldmx4(a[mi][t], smem_u32(&As[wm + mi * 16 + (lane & 15)][t * 16 + (lane >> 4) * 8]));

    float s_run[4] = {0.f, 0.f, 0.f, 0.f};

    for (int c = 0; c < NITER; c++) {
        __syncthreads();
        if (c + 1 < NITER) {
            int q1 = qbase + (c + 1) * 128;
            int bufn = (c + 1) & 1;
#pragma unroll
            for (int i = 0; i < 4; i++) {
                int idx = tid + i * 256;
                int r = idx >> 3, c8 = idx & 7;
                cpa16(smem_u32(&Bs[bufn][r][c8 * 8]), Qp + (size_t)(q1 + r) * Dh + c8 * 8);
            }
            cpa_commit();
            cpa_wait<1>();
        } else {
            cpa_wait<0>();
        }
        __syncthreads();
        int buf = c & 1;

        float acc[2][8][4] = {};
#pragma unroll
        for (int t = 0; t < 4; t++) {
            unsigned b[8][2];
#pragma unroll
            for (int p = 0; p < 4; p++) {
                unsigned r4[4];
                ldmx4(r4, smem_u32(&Bs[buf][wn + p * 16 + (lane & 7) + (lane >> 4) * 8]
                                         [t * 16 + ((lane >> 3) & 1) * 8]));
                b[2 * p][0] = r4[0]; b[2 * p][1] = r4[1];
                b[2 * p + 1][0] = r4[2]; b[2 * p + 1][1] = r4[3];
            }
#pragma unroll
            for (int mi = 0; mi < 2; mi++)
#pragma unroll
                for (int nj = 0; nj < 8; nj++)
                    mma16816(acc[mi][nj], a[mi][t], b[nj]);
        }
#pragma unroll
        for (int mi = 0; mi < 2; mi++) {
            __half2 h0 = __float2half2_rn(0.f), h1 = __float2half2_rn(0.f);
#pragma unroll
            for (int nj = 0; nj < 8; nj++) {
                h0 = __hadd2(h0, h2exp2(__floats2half2_rn(acc[mi][nj][0], acc[mi][nj][1])));
                h1 = __hadd2(h1, h2exp2(__floats2half2_rn(acc[mi][nj][2], acc[mi][nj][3])));
            }
            float2 f0 = __half22float2(h0), f1 = __half22float2(h1);
            s_run[mi * 2 + 0] += f0.x + f0.y;
            s_run[mi * 2 + 1] += f1.x + f1.y;
        }
    }

#pragma unroll
    for (int off = 1; off <= 2; off <<= 1)
#pragma unroll
        for (int slot = 0; slot < 4; slot++)
            s_run[slot] += __shfl_xor_sync(0xffffffffu, s_run[slot], off);
    __syncthreads();
    if ((lane & 3) == 0) {
#pragma unroll
        for (int mi = 0; mi < 2; mi++)
#pragma unroll
            for (int half = 0; half < 2; half++) {
                int slot = mi * 2 + half;
                int row = wm + mi * 16 + half * 8 + (lane >> 2);
                sred[wid & 1][row] = s_run[slot];
            }
    }
    __syncthreads();
    if (tid < 128)
        g_stp[(qs * NH + nh) * Ss + k0 + tid] = sred[0][tid] + sred[1][tid];
}

// ---------------- combine partial sums + scale V by inv_k (in place) ----------------
__global__ void k_stvs() {
    int base = blockIdx.x * 64;
    __shared__ float sinv[64];
    int tid = threadIdx.x;
    if (tid < 64) {
        int i = base + tid;
        float s = 0.f;
#pragma unroll
        for (int qs = 0; qs < QSPLIT; qs++)
            s += g_stp[qs * NH * Ss + i];
        sinv[tid] = 1.0f / s;
    }
    __syncthreads();
    __half2* V2 = (__half2*)g_Vh;
#pragma unroll
    for (int j = 0; j < 8; j++) {
        int idx = tid + j * 256;
        int row = idx >> 5, c2 = idx & 31;
        float inv = sinv[row];
        size_t o = (size_t)(base + row) * 32 + c2;
        float2 vf = __half22float2(V2[o]);
        V2[o] = __floats2half2_rn(vf.x * inv, vf.y * inv);
    }
}

// ---------------- pass 2: flash attn; 3-stage cp.async, single barrier/iter ----------------
__global__ __launch_bounds__(256, 2) void k_flash() {
    int nh = blockIdx.y;
    int ks = blockIdx.z;
    int q0 = blockIdx.x * 128;
    const __half* Qp = g_Qh + (size_t)nh * Ss * Dh;
    const __half* Kp = g_Kh + (size_t)nh * Ss * Dh;
    const __half* Vp = g_Vh + (size_t)nh * Ss * Dh;
    constexpr int NITER = Ss / 32 / KSPLIT;   // 32
    int kbase = ks * (Ss / KSPLIT);

    __shared__ __half Qs[128][72];
    __shared__ __half Ks[3][32][72];
    __shared__ __half Vs[3][32][72];

    int tid = threadIdx.x, lane = tid & 31, wid = tid >> 5;
    int wm = wid * 16;
    int lr = tid >> 3, lc8 = tid & 7;   // cp.async lane mapping: 32 rows x 8 cols of 16B

#pragma unroll
    for (int i = 0; i < 4; i++) {
        int idx = tid + i * 256;
        int r = idx >> 3, c8 = idx & 7;
        *(float4*)&Qs[r][c8 * 8] = *(const float4*)(Qp + (size_t)(q0 + r) * Dh + c8 * 8);
    }
    // prologue: stages 0 and 1
    cpa16(smem_u32(&Ks[0][lr][lc8 * 8]), Kp + (size_t)(kbase + lr) * Dh + lc8 * 8);
    cpa16(smem_u32(&Vs[0][lr][lc8 * 8]), Vp + (size_t)(kbase + lr) * Dh + lc8 * 8);
    cpa_commit();
    cpa16(smem_u32(&Ks[1][lr][lc8 * 8]), Kp + (size_t)(kbase + 32 + lr) * Dh + lc8 * 8);
    cpa16(smem_u32(&Vs[1][lr][lc8 * 8]), Vp + (size_t)(kbase + 32 + lr) * Dh + lc8 * 8);
    cpa_commit();
    __syncthreads();

    unsigned aq[4][4];
#pragma unroll
    for (int t = 0; t < 4; t++)
        ldmx4(aq[t], smem_u32(&Qs[wm + (lane & 15)][t * 16 + (lane >> 4) * 8]));

    float accO[8][4] = {};

    for (int c = 0; c < NITER; c++) {
        if (c + 1 < NITER) cpa_wait<1>(); else cpa_wait<0>();
        __syncthreads();
        if (c + 2 < NITER) {
            int kb2 = kbase + (c + 2) * 32;
            int bufn = (c + 2) % 3;
            cpa16(smem_u32(&Ks[bufn][lr][lc8 * 8]), Kp + (size_t)(kb2 + lr) * Dh + lc8 * 8);
            cpa16(smem_u32(&Vs[bufn][lr][lc8 * 8]), Vp + (size_t)(kb2 + lr) * Dh + lc8 * 8);
            cpa_commit();
        }
        int buf = c % 3;

        float accS[4][4] = {};
#pragma unroll
        for (int t = 0; t < 4; t++) {
            unsigned b[4][2];
#pragma unroll
            for (int p = 0; p < 2; p++) {
                unsigned r4[4];
                ldmx4(r4, smem_u32(&Ks[buf][p * 16 + (lane & 7) + (lane >> 4) * 8]
                                         [t * 16 + ((lane >> 3) & 1) * 8]));
                b[2 * p][0] = r4[0]; b[2 * p][1] = r4[1];
                b[2 * p + 1][0] = r4[2]; b[2 * p + 1][1] = r4[3];
            }
#pragma unroll
            for (int nj = 0; nj < 4; nj++)
                mma16816(accS[nj], aq[t], b[nj]);
        }

        unsigned ap[2][4];
#pragma unroll
        for (int nj = 0; nj < 4; nj++) {
            __half2 e0 = h2exp2(__floats2half2_rn(accS[nj][0], accS[nj][1]));
            __half2 e1 = h2exp2(__floats2half2_rn(accS[nj][2], accS[nj][3]));
            int t = nj >> 1, w2 = (nj & 1) * 2;
            ap[t][w2]     = *(unsigned*)&e0;
            ap[t][w2 + 1] = *(unsigned*)&e1;
        }

#pragma unroll
        for (int t = 0; t < 2; t++) {
            unsigned bv[8][2];
#pragma unroll
            for (int p = 0; p < 4; p++) {
                unsigned r4[4];
                ldmx4t(r4, smem_u32(&Vs[buf][t * 16 + (lane & 7) + ((lane >> 3) & 1) * 8]
                                          [p * 16 + (lane >> 4) * 8]));
                bv[2 * p][0] = r4[0]; bv[2 * p][1] = r4[1];
                bv[2 * p + 1][0] = r4[2]; bv[2 * p + 1][1] = r4[3];
            }
#pragma unroll
            for (int dj = 0; dj < 8; dj++)
                mma16816(accO[dj], ap[t], bv[dj]);
        }
    }

    float* Po = g_po + ((size_t)(ks * NH + nh) * Ss) * Dh;
#pragma unroll
    for (int dj = 0; dj < 8; dj++) {
        int q = q0 + wm + (lane >> 2);
        int col = dj * 8 + 2 * (lane & 3);
        *(float2*)(Po + (size_t)q * Dh + col) = make_float2(accO[dj][0], accO[dj][1]);
        *(float2*)(Po + (size_t)(q + 8) * Dh + col) = make_float2(accO[dj][2], accO[dj][3]);
    }
}

// ---------------- MLP GEMMs, fp16 mma, 64x64 blocks ----------------
template <int MODE>
__global__ __launch_bounds__(256) void k_mlp(const float* __restrict__ bias) {
    int m0 = blockIdx.x * 64;
    int n0 = blockIdx.y * 64;
    const __half* A = (MODE == 0) ? g_uh : g_h1h;
    const __half* W = (MODE == 0) ? g_W1h : g_W2h;

    __shared__ __half As[64][88];
    __shared__ __half Bs[64][88];
    int tid = threadIdx.x, lane = tid & 31, wid = tid >> 5;
    int wm = (wid >> 1) * 16;
    int wn = (wid & 1) * 32;
    float acc[4][4] = {};

    for (int kb = 0; kb < Cc; kb += 64) {
#pragma unroll
        for (int i = 0; i < 2; i++) {
            int idx = tid + i * 256;
            int r = idx >> 3, c8 = idx & 7;
            *(float4*)&As[r][c8 * 8] = *(const float4*)(A + (size_t)(m0 + r) * Cc + kb + c8 * 8);
            *(float4*)&Bs[r][c8 * 8] = *(const float4*)(W + (size_t)(kb + r) * Cc + n0 + c8 * 8);
        }
        __syncthreads();
#pragma unroll
        for (int kk = 0; kk < 64; kk += 16) {
            unsigned a[4], b[4][2];
            ldmx4(a, smem_u32(&As[wm + (lane & 15)][kk + (lane >> 4) * 8]));
#pragma unroll
            for (int p = 0; p < 2; p++) {
                unsigned r4[4];
                ldmx4t(r4, smem_u32(&Bs[kk + (lane & 7) + ((lane >> 3) & 1) * 8]
                                       [wn + p * 16 + (lane >> 4) * 8]));
                b[2 * p][0] = r4[0]; b[2 * p][1] = r4[1];
                b[2 * p + 1][0] = r4[2]; b[2 * p + 1][1] = r4[3];
            }
#pragma unroll
            for (int nj = 0; nj < 4; nj++)
                mma16816(acc[nj], a, b[nj]);
        }
        __syncthreads();
    }
#pragma unroll
    for (int half = 0; half < 2; half++) {
        int row = m0 + wm + half * 8 + (lane >> 2);
#pragma unroll
        for (int nj = 0; nj < 4; nj++) {
            int col = n0 + wn + nj * 8 + 2 * (lane & 3);
            float v0 = acc[nj][2 * half]     + bias[col];
            float v1 = acc[nj][2 * half + 1] + bias[col + 1];
            if (MODE == 0) {
                v0 = 0.5f * v0 * (1.0f + erff(v0 * 0.70710678118654752f));
                v1 = 0.5f * v1 * (1.0f + erff(v1 * 0.70710678118654752f));
                *(__half2*)(g_h1h + (size_t)row * Cc + col) = __floats2half2_rn(v0, v1);
            } else {
                v0 += g_attn[(size_t)row * Cc + col];
                v1 += g_attn[(size_t)row * Cc + col + 1];
                *(float2*)(g_o + (size_t)row * Cc + col) = make_float2(v0, v1);
            }
        }
    }
}

// ---------------- launch ----------------
extern "C" void kernel_launch(void* const* d_in, const int* in_sizes, int n_in,
                              void* d_out, int out_size) {
    const float* x     = (const float*)d_in[0];
    const float* ln1_w = (const float*)d_in[1];
    const float* ln1_b = (const float*)d_in[2];
    const float* WQ    = (const float*)d_in[3];
    const float* WK    = (const float*)d_in[4];
    const float* WV    = (const float*)d_in[5];
    const float* ln2_w = (const float*)d_in[6];
    const float* ln2_b = (const float*)d_in[7];
    const float* W1    = (const float*)d_in[8];
    const float* b1    = (const float*)d_in[9];
    const float* W2    = (const float*)d_in[10];
    const float* b2    = (const float*)d_in[11];
    float* out = (float*)d_out;

    k_tin_ln<<<dim3(Ss / 32, Nb), dim3(32, 8)>>>(x, ln1_w, ln1_b);
    k_cvtw<<<Cc * Cc / 256, 256>>>(W1, W2, WQ, WK, WV);

    k_qkv<<<dim3(Ss / 128, 12, Nb), 256>>>();

    k_stats<<<dim3(Ss / 128, NH, QSPLIT), 256>>>();
    k_stvs<<<NH * Ss / 64, 256>>>();
    k_flash<<<dim3(Ss / 128, NH, KSPLIT), 256>>>();

    k_oln<<<Nb * Ss, 256>>>(ln2_w, ln2_b);
    k_mlp<0><<<dim3(128, 4), 256>>>(b1);
    k_mlp<1><<<dim3(128, 4), 256>>>(b2);

    k_transpose_out<<<dim3(Ss / 32, Cc / 32, Nb), dim3(32, 8)>>>(out);
}

// round 11
// speedup vs baseline: 1.0272x; 1.0272x over previous
#include <cuda_runtime.h>
#include <cuda_fp16.h>
#include <cstdint>
#include <stdint.h>
#include <math.h>

// ---------------- problem constants ----------------
constexpr int Nb = 2;
constexpr int Cc = 256;
constexpr int Ss = 4096;
constexpr int Hh = 4;
constexpr int Dh = 64;
constexpr int NH = Nb * Hh;
constexpr float EPSV = 1e-5f;
constexpr float QSCALE = (1.0f / 64.0f) * 1.4426950408889634f;  // folded into WQ
constexpr int QSPLIT = 4;
constexpr int KSPLIT = 4;

// ---------------- device scratch ----------------
__device__ float  g_r    [Nb * Ss * Cc];
__device__ __half g_normh[Nb * Ss * Cc];
__device__ __half g_Qh   [NH * Ss * Dh];
__device__ __half g_Kh   [NH * Ss * Dh];
__device__ __half g_Vh   [NH * Ss * Dh];   // post-stats: scaled by inv_k
__device__ float  g_stp  [QSPLIT * NH * Ss];
__device__ float  g_po   [KSPLIT * NH * Ss * Dh];
__device__ float  g_attn [Nb * Ss * Cc];
__device__ __half g_uh   [Nb * Ss * Cc];
__device__ __half g_h1h  [Nb * Ss * Cc];
__device__ __half g_W1h  [Cc * Cc];
__device__ __half g_W2h  [Cc * Cc];
__device__ __half g_WQh  [Hh * Cc * Dh];   // pre-scaled by QSCALE
__device__ __half g_WKh  [Hh * Cc * Dh];
__device__ __half g_WVh  [Hh * Cc * Dh];
__device__ float  g_o    [Nb * Ss * Cc];

// ---------------- helpers ----------------
__device__ __forceinline__ unsigned smem_u32(const void* p) {
    return (unsigned)__cvta_generic_to_shared(p);
}
__device__ __forceinline__ void ldmx4(unsigned* r, unsigned a) {
    asm volatile("ldmatrix.sync.aligned.m8n8.x4.shared.b16 {%0,%1,%2,%3},[%4];"
                 : "=r"(r[0]), "=r"(r[1]), "=r"(r[2]), "=r"(r[3]) : "r"(a));
}
__device__ __forceinline__ void ldmx4t(unsigned* r, unsigned a) {
    asm volatile("ldmatrix.sync.aligned.m8n8.x4.trans.shared.b16 {%0,%1,%2,%3},[%4];"
                 : "=r"(r[0]), "=r"(r[1]), "=r"(r[2]), "=r"(r[3]) : "r"(a));
}
__device__ __forceinline__ void mma16816(float* c, const unsigned* a, const unsigned* b) {
    asm volatile(
        "mma.sync.aligned.m16n8k16.row.col.f32.f16.f16.f32 "
        "{%0,%1,%2,%3},{%4,%5,%6,%7},{%8,%9},{%0,%1,%2,%3};"
        : "+f"(c[0]), "+f"(c[1]), "+f"(c[2]), "+f"(c[3])
        : "r"(a[0]), "r"(a[1]), "r"(a[2]), "r"(a[3]), "r"(b[0]), "r"(b[1]));
}
// fp16-accumulator variant: D/C are 2 regs of half2
__device__ __forceinline__ void mma16816h(unsigned* c, const unsigned* a, const unsigned* b) {
    asm volatile(
        "mma.sync.aligned.m16n8k16.row.col.f16.f16.f16.f16 "
        "{%0,%1},{%2,%3,%4,%5},{%6,%7},{%0,%1};"
        : "+r"(c[0]), "+r"(c[1])
        : "r"(a[0]), "r"(a[1]), "r"(a[2]), "r"(a[3]), "r"(b[0]), "r"(b[1]));
}
__device__ __forceinline__ void cpa16(unsigned dst, const void* src) {
    asm volatile("cp.async.ca.shared.global [%0], [%1], 16;" :: "r"(dst), "l"(src));
}
__device__ __forceinline__ void cpa_commit() {
    asm volatile("cp.async.commit_group;");
}
template <int N>
__device__ __forceinline__ void cpa_wait() {
    asm volatile("cp.async.wait_group %0;" :: "n"(N));
}

// ---------------- fused: transpose x[n,c,s] -> r[n,s,c] + LN1 -> normh ----------------
__global__ void k_tin_ln(const float* __restrict__ x,
                         const float* __restrict__ w, const float* __restrict__ b) {
    __shared__ float t[256][33];
    int n = blockIdx.y, s0 = blockIdx.x * 32;
    int tx = threadIdx.x, ty = threadIdx.y;
#pragma unroll
    for (int i = 0; i < 32; i++)
        t[ty + 8 * i][tx] = x[((size_t)(n * Cc + ty + 8 * i)) * Ss + s0 + tx];
    __syncthreads();
    int lane = tx;
#pragma unroll
    for (int j = 0; j < 4; j++) {
        int s = ty * 4 + j;
        float vals[8];
        float s1 = 0.f, s2 = 0.f;
#pragma unroll
        for (int u = 0; u < 8; u++) {
            float v = t[lane + 32 * u][s];
            vals[u] = v; s1 += v; s2 += v * v;
        }
#pragma unroll
        for (int o = 16; o; o >>= 1) {
            s1 += __shfl_xor_sync(0xffffffffu, s1, o);
            s2 += __shfl_xor_sync(0xffffffffu, s2, o);
        }
        float mean = s1 * (1.0f / Cc);
        float rstd = rsqrtf(s2 * (1.0f / Cc) - mean * mean + EPSV);
        size_t rowo = ((size_t)n * Ss + s0 + s) * Cc;
#pragma unroll
        for (int u = 0; u < 8; u++) {
            int c = lane + 32 * u;
            g_r[rowo + c] = vals[u];
            g_normh[rowo + c] = __float2half((vals[u] - mean) * rstd * w[c] + b[c]);
        }
    }
}

// ---------------- transpose out ----------------
__global__ void k_transpose_out(float* __restrict__ out) {
    __shared__ float t[32][33];
    int n = blockIdx.z;
    int s0 = blockIdx.x * 32, c0 = blockIdx.y * 32;
    int tx = threadIdx.x, ty = threadIdx.y;
#pragma unroll
    for (int i = 0; i < 4; i++)
        t[ty + 8 * i][tx] = g_o[((size_t)(n * Ss + s0 + ty + 8 * i)) * Cc + c0 + tx];
    __syncthreads();
#pragma unroll
    for (int i = 0; i < 4; i++)
        out[((size_t)(n * Cc + c0 + ty + 8 * i)) * Ss + s0 + tx] = t[tx][ty + 8 * i];
}

// ---------------- all weights fp32 -> fp16 once ----------------
__global__ void k_cvtw(const float* __restrict__ W1, const float* __restrict__ W2,
                       const float* __restrict__ WQ, const float* __restrict__ WK,
                       const float* __restrict__ WV) {
    int i = blockIdx.x * 256 + threadIdx.x;
    g_W1h[i] = __float2half(W1[i]);
    g_W2h[i] = __float2half(W2[i]);
    g_WQh[i] = __float2half(WQ[i] * QSCALE);
    g_WKh[i] = __float2half(WK[i]);
    g_WVh[i] = __float2half(WV[i]);
}

// ---------------- fused: O-combine + residual + LN2 -> g_attn, g_uh ----------------
__global__ void k_oln(const float* __restrict__ w, const float* __restrict__ b) {
    int row = blockIdx.x;
    int t = threadIdx.x;
    int n = row >> 12, q = row & 4095;
    int h = t >> 6, d = t & 63;
    int nh = n * 4 + h;
    float val = 0.f;
#pragma unroll
    for (int ks = 0; ks < KSPLIT; ks++)
        val += g_po[((size_t)(ks * NH + nh) * Ss + q) * Dh + d];
    size_t idx = (size_t)row * Cc + t;
    g_attn[idx] = val;
    float v = val + g_r[idx];

    float s1 = v, s2 = v * v;
#pragma unroll
    for (int o = 16; o; o >>= 1) {
        s1 += __shfl_xor_sync(0xffffffffu, s1, o);
        s2 += __shfl_xor_sync(0xffffffffu, s2, o);
    }
    __shared__ float sm1[8], sm2[8];
    __shared__ float mb, rb;
    int w8 = t >> 5, lane = t & 31;
    if (!lane) { sm1[w8] = s1; sm2[w8] = s2; }
    __syncthreads();
    if (t == 0) {
        float a = 0.f, qq = 0.f;
#pragma unroll
        for (int i = 0; i < 8; i++) { a += sm1[i]; qq += sm2[i]; }
        float mean = a * (1.0f / Cc);
        mb = mean;
        rb = rsqrtf(qq * (1.0f / Cc) - mean * mean + EPSV);
    }
    __syncthreads();
    g_uh[idx] = __float2half((v - mb) * rb * w[t] + b[t]);
}

// ---------------- QKV projection, fp16 mma, pre-converted weights ----------------
__global__ __launch_bounds__(256) void k_qkv() {
    int which = blockIdx.y >> 2;
    int h = blockIdx.y & 3;
    int n = blockIdx.z;
    int m0 = blockIdx.x * 128;
    const __half* W = (which == 0 ? g_WQh : which == 1 ? g_WKh : g_WVh) + h * Cc * Dh;
    __half* Out = (which == 0 ? g_Qh : which == 1 ? g_Kh : g_Vh) + (size_t)(n * 4 + h) * Ss * Dh;
    const __half* A = g_normh + (size_t)n * Ss * Cc;

    __shared__ __half As[128][88];
    __shared__ __half Bs[64][88];
    int tid = threadIdx.x, lane = tid & 31, wid = tid >> 5;
    int wm = (wid >> 1) * 32;
    int wn = (wid & 1) * 32;
    float acc[2][4][4] = {};

    for (int kb = 0; kb < Cc; kb += 64) {
#pragma unroll
        for (int i = 0; i < 4; i++) {
            int idx = tid + i * 256;
            int r = idx >> 3, c8 = idx & 7;
            *(float4*)&As[r][c8 * 8] = *(const float4*)(A + (size_t)(m0 + r) * Cc + kb + c8 * 8);
        }
#pragma unroll
        for (int i = 0; i < 2; i++) {
            int idx = tid + i * 256;
            int r = idx >> 3, c8 = idx & 7;
            *(float4*)&Bs[r][c8 * 8] = *(const float4*)(W + (size_t)(kb + r) * Dh + c8 * 8);
        }
        __syncthreads();
#pragma unroll
        for (int kk = 0; kk < 64; kk += 16) {
            unsigned a[2][4], b[4][2];
#pragma unroll
            for (int mi = 0; mi < 2; mi++)
                ldmx4(a[mi], smem_u32(&As[wm + mi * 16 + (lane & 15)][kk + (lane >> 4) * 8]));
#pragma unroll
            for (int p = 0; p < 2; p++) {
                unsigned r4[4];
                ldmx4t(r4, smem_u32(&Bs[kk + (lane & 7) + ((lane >> 3) & 1) * 8]
                                       [wn + p * 16 + (lane >> 4) * 8]));
                b[2 * p][0] = r4[0]; b[2 * p][1] = r4[1];
                b[2 * p + 1][0] = r4[2]; b[2 * p + 1][1] = r4[3];
            }
#pragma unroll
            for (int mi = 0; mi < 2; mi++)
#pragma unroll
                for (int nj = 0; nj < 4; nj++)
                    mma16816(acc[mi][nj], a[mi], b[nj]);
        }
        __syncthreads();
    }
#pragma unroll
    for (int mi = 0; mi < 2; mi++) {
        int r = m0 + wm + mi * 16 + (lane >> 2);
#pragma unroll
        for (int nj = 0; nj < 4; nj++) {
            int c = wn + nj * 8 + 2 * (lane & 3);
            *(__half2*)(Out + (size_t)r * Dh + c) =
                __floats2half2_rn(acc[mi][nj][0], acc[mi][nj][1]);
            *(__half2*)(Out + (size_t)(r + 8) * Dh + c) =
                __floats2half2_rn(acc[mi][nj][2], acc[mi][nj][3]);
        }
    }
}

// ---------------- pass 1: per-k partial sum of exp2(S), f16 accumulators ----------------
__global__ __launch_bounds__(256) void k_stats() {
    int nh = blockIdx.y;
    int qs = blockIdx.z;
    int k0 = blockIdx.x * 128;
    const __half* Kp = g_Kh + (size_t)nh * Ss * Dh;
    const __half* Qp = g_Qh + (size_t)nh * Ss * Dh;
    constexpr int NITER = Ss / 128 / QSPLIT;   // 8
    int qbase = qs * (Ss / QSPLIT);

    __shared__ __half As[128][72];
    __shared__ __half Bs[2][128][72];
    __shared__ float sred[2][128];

    int tid = threadIdx.x, lane = tid & 31, wid = tid >> 5;
    int wm = (wid >> 1) * 32;
    int wn = (wid & 1) * 64;

#pragma unroll
    for (int i = 0; i < 4; i++) {
        int idx = tid + i * 256;
        int r = idx >> 3, c8 = idx & 7;
        *(float4*)&As[r][c8 * 8] = *(const float4*)(Kp + (size_t)(k0 + r) * Dh + c8 * 8);
    }
#pragma unroll
    for (int i = 0; i < 4; i++) {
        int idx = tid + i * 256;
        int r = idx >> 3, c8 = idx & 7;
        cpa16(smem_u32(&Bs[0][r][c8 * 8]), Qp + (size_t)(qbase + r) * Dh + c8 * 8);
    }
    cpa_commit();
    __syncthreads();

    unsigned a[2][4][4];
#pragma unroll
    for (int mi = 0; mi < 2; mi++)
#pragma unroll
        for (int t = 0; t < 4; t++)
            ldmx4(a[mi][t], smem_u32(&As[wm + mi * 16 + (lane & 15)][t * 16 + (lane >> 4) * 8]));

    float s_run[4] = {0.f, 0.f, 0.f, 0.f};

    for (int c = 0; c < NITER; c++) {
        __syncthreads();
        if (c + 1 < NITER) {
            int q1 = qbase + (c + 1) * 128;
            int bufn = (c + 1) & 1;
#pragma unroll
            for (int i = 0; i < 4; i++) {
                int idx = tid + i * 256;
                int r = idx >> 3, c8 = idx & 7;
                cpa16(smem_u32(&Bs[bufn][r][c8 * 8]), Qp + (size_t)(q1 + r) * Dh + c8 * 8);
            }
            cpa_commit();
            cpa_wait<1>();
        } else {
            cpa_wait<0>();
        }
        __syncthreads();
        int buf = c & 1;

        unsigned acc[2][8][2] = {};   // f16x2 accumulators, zero bits == +0.0h
#pragma unroll
        for (int t = 0; t < 4; t++) {
            unsigned b[8][2];
#pragma unroll
            for (int p = 0; p < 4; p++) {
                unsigned r4[4];
                ldmx4(r4, smem_u32(&Bs[buf][wn + p * 16 + (lane & 7) + (lane >> 4) * 8]
                                         [t * 16 + ((lane >> 3) & 1) * 8]));
                b[2 * p][0] = r4[0]; b[2 * p][1] = r4[1];
                b[2 * p + 1][0] = r4[2]; b[2 * p + 1][1] = r4[3];
            }
#pragma unroll
            for (int mi = 0; mi < 2; mi++)
#pragma unroll
                for (int nj = 0; nj < 8; nj++)
                    mma16816h(acc[mi][nj], a[mi][t], b[nj]);
        }
        // sum exp2(S): f16 acc regs are half2 in-place -> no converts
#pragma unroll
        for (int mi = 0; mi < 2; mi++) {
            __half2 h0 = __float2half2_rn(0.f), h1 = __float2half2_rn(0.f);
#pragma unroll
            for (int nj = 0; nj < 8; nj++) {
                h0 = __hadd2(h0, h2exp2(*(__half2*)&acc[mi][nj][0]));
                h1 = __hadd2(h1, h2exp2(*(__half2*)&acc[mi][nj][1]));
            }
            float2 f0 = __half22float2(h0), f1 = __half22float2(h1);
            s_run[mi * 2 + 0] += f0.x + f0.y;   // row (lane>>2): two q-columns
            s_run[mi * 2 + 1] += f1.x + f1.y;   // row +8
        }
    }

#pragma unroll
    for (int off = 1; off <= 2; off <<= 1)
#pragma unroll
        for (int slot = 0; slot < 4; slot++)
            s_run[slot] += __shfl_xor_sync(0xffffffffu, s_run[slot], off);
    __syncthreads();
    if ((lane & 3) == 0) {
#pragma unroll
        for (int mi = 0; mi < 2; mi++)
#pragma unroll
            for (int half = 0; half < 2; half++) {
                int slot = mi * 2 + half;
                int row = wm + mi * 16 + half * 8 + (lane >> 2);
                sred[wid & 1][row] = s_run[slot];
            }
    }
    __syncthreads();
    if (tid < 128)
        g_stp[(qs * NH + nh) * Ss + k0 + tid] = sred[0][tid] + sred[1][tid];
}

// ---------------- combine partial sums + scale V by inv_k (in place) ----------------
__global__ void k_stvs() {
    int base = blockIdx.x * 64;
    __shared__ float sinv[64];
    int tid = threadIdx.x;
    if (tid < 64) {
        int i = base + tid;
        float s = 0.f;
#pragma unroll
        for (int qs = 0; qs < QSPLIT; qs++)
            s += g_stp[qs * NH * Ss + i];
        sinv[tid] = 1.0f / s;
    }
    __syncthreads();
    __half2* V2 = (__half2*)g_Vh;
#pragma unroll
    for (int j = 0; j < 8; j++) {
        int idx = tid + j * 256;
        int row = idx >> 5, c2 = idx & 31;
        float inv = sinv[row];
        size_t o = (size_t)(base + row) * 32 + c2;
        float2 vf = __half22float2(V2[o]);
        V2[o] = __floats2half2_rn(vf.x * inv, vf.y * inv);
    }
}

// ---------------- pass 2: flash attn; f16-acc S, P = exp2(S) in place ----------------
__global__ __launch_bounds__(256, 2) void k_flash() {
    int nh = blockIdx.y;
    int ks = blockIdx.z;
    int q0 = blockIdx.x * 128;
    const __half* Qp = g_Qh + (size_t)nh * Ss * Dh;
    const __half* Kp = g_Kh + (size_t)nh * Ss * Dh;
    const __half* Vp = g_Vh + (size_t)nh * Ss * Dh;
    constexpr int NITER = Ss / 32 / KSPLIT;   // 32
    int kbase = ks * (Ss / KSPLIT);

    __shared__ __half Qs[128][72];
    __shared__ __half Ks[2][32][72];
    __shared__ __half Vs[2][32][72];

    int tid = threadIdx.x, lane = tid & 31, wid = tid >> 5;
    int wm = wid * 16;
    int lr = tid >> 3, lc8 = tid & 7;

#pragma unroll
    for (int i = 0; i < 4; i++) {
        int idx = tid + i * 256;
        int r = idx >> 3, c8 = idx & 7;
        *(float4*)&Qs[r][c8 * 8] = *(const float4*)(Qp + (size_t)(q0 + r) * Dh + c8 * 8);
    }
    cpa16(smem_u32(&Ks[0][lr][lc8 * 8]), Kp + (size_t)(kbase + lr) * Dh + lc8 * 8);
    cpa16(smem_u32(&Vs[0][lr][lc8 * 8]), Vp + (size_t)(kbase + lr) * Dh + lc8 * 8);
    cpa_commit();
    __syncthreads();

    unsigned aq[4][4];
#pragma unroll
    for (int t = 0; t < 4; t++)
        ldmx4(aq[t], smem_u32(&Qs[wm + (lane & 15)][t * 16 + (lane >> 4) * 8]));

    float accO[8][4] = {};

    for (int c = 0; c < NITER; c++) {
        __syncthreads();
        if (c + 1 < NITER) {
            int kb1 = kbase + (c + 1) * 32;
            int bufn = (c + 1) & 1;
            cpa16(smem_u32(&Ks[bufn][lr][lc8 * 8]), Kp + (size_t)(kb1 + lr) * Dh + lc8 * 8);
            cpa16(smem_u32(&Vs[bufn][lr][lc8 * 8]), Vp + (size_t)(kb1 + lr) * Dh + lc8 * 8);
            cpa_commit();
            cpa_wait<1>();
        } else {
            cpa_wait<0>();
        }
        __syncthreads();
        int buf = c & 1;

        unsigned accS[4][2] = {};    // f16x2 S accumulators
#pragma unroll
        for (int t = 0; t < 4; t++) {
            unsigned b[4][2];
#pragma unroll
            for (int p = 0; p < 2; p++) {
                unsigned r4[4];
                ldmx4(r4, smem_u32(&Ks[buf][p * 16 + (lane & 7) + (lane >> 4) * 8]
                                         [t * 16 + ((lane >> 3) & 1) * 8]));
                b[2 * p][0] = r4[0]; b[2 * p][1] = r4[1];
                b[2 * p + 1][0] = r4[2]; b[2 * p + 1][1] = r4[3];
            }
#pragma unroll
            for (int nj = 0; nj < 4; nj++)
                mma16816h(accS[nj], aq[t], b[nj]);
        }

        // P = exp2(S): regs already half2 in A-fragment layout
        unsigned ap[2][4];
#pragma unroll
        for (int nj = 0; nj < 4; nj++) {
            __half2 e0 = h2exp2(*(__half2*)&accS[nj][0]);   // (row, col pair)
            __half2 e1 = h2exp2(*(__half2*)&accS[nj][1]);   // (row+8, col pair)
            int t = nj >> 1, w2 = (nj & 1) * 2;
            ap[t][w2]     = *(unsigned*)&e0;
            ap[t][w2 + 1] = *(unsigned*)&e1;
        }

#pragma unroll
        for (int t = 0; t < 2; t++) {
            unsigned bv[8][2];
#pragma unroll
            for (int p = 0; p < 4; p++) {
                unsigned r4[4];
                ldmx4t(r4, smem_u32(&Vs[buf][t * 16 + (lane & 7) + ((lane >> 3) & 1) * 8]
                                          [p * 16 + (lane >> 4) * 8]));
                bv[2 * p][0] = r4[0]; bv[2 * p][1] = r4[1];
                bv[2 * p + 1][0] = r4[2]; bv[2 * p + 1][1] = r4[3];
            }
#pragma unroll
            for (int dj = 0; dj < 8; dj++)
                mma16816(accO[dj], ap[t], bv[dj]);
        }
    }

    float* Po = g_po + ((size_t)(ks * NH + nh) * Ss) * Dh;
#pragma unroll
    for (int dj = 0; dj < 8; dj++) {
        int q = q0 + wm + (lane >> 2);
        int col = dj * 8 + 2 * (lane & 3);
        *(float2*)(Po + (size_t)q * Dh + col) = make_float2(accO[dj][0], accO[dj][1]);
        *(float2*)(Po + (size_t)(q + 8) * Dh + col) = make_float2(accO[dj][2], accO[dj][3]);
    }
}

// ---------------- MLP GEMMs, fp16 mma, 64x64 blocks ----------------
template <int MODE>
__global__ __launch_bounds__(256) void k_mlp(const float* __restrict__ bias) {
    int m0 = blockIdx.x * 64;
    int n0 = blockIdx.y * 64;
    const __half* A = (MODE == 0) ? g_uh : g_h1h;
    const __half* W = (MODE == 0) ? g_W1h : g_W2h;

    __shared__ __half As[64][88];
    __shared__ __half Bs[64][88];
    int tid = threadIdx.x, lane = tid & 31, wid = tid >> 5;
    int wm = (wid >> 1) * 16;
    int wn = (wid & 1) * 32;
    float acc[4][4] = {};

    for (int kb = 0; kb < Cc; kb += 64) {
#pragma unroll
        for (int i = 0; i < 2; i++) {
            int idx = tid + i * 256;
            int r = idx >> 3, c8 = idx & 7;
            *(float4*)&As[r][c8 * 8] = *(const float4*)(A + (size_t)(m0 + r) * Cc + kb + c8 * 8);
            *(float4*)&Bs[r][c8 * 8] = *(const float4*)(W + (size_t)(kb + r) * Cc + n0 + c8 * 8);
        }
        __syncthreads();
#pragma unroll
        for (int kk = 0; kk < 64; kk += 16) {
            unsigned a[4], b[4][2];
            ldmx4(a, smem_u32(&As[wm + (lane & 15)][kk + (lane >> 4) * 8]));
#pragma unroll
            for (int p = 0; p < 2; p++) {
                unsigned r4[4];
                ldmx4t(r4, smem_u32(&Bs[kk + (lane & 7) + ((lane >> 3) & 1) * 8]
                                       [wn + p * 16 + (lane >> 4) * 8]));
                b[2 * p][0] = r4[0]; b[2 * p][1] = r4[1];
                b[2 * p + 1][0] = r4[2]; b[2 * p + 1][1] = r4[3];
            }
#pragma unroll
            for (int nj = 0; nj < 4; nj++)
                mma16816(acc[nj], a, b[nj]);
        }
        __syncthreads();
    }
#pragma unroll
    for (int half = 0; half < 2; half++) {
        int row = m0 + wm + half * 8 + (lane >> 2);
#pragma unroll
        for (int nj = 0; nj < 4; nj++) {
            int col = n0 + wn + nj * 8 + 2 * (lane & 3);
            float v0 = acc[nj][2 * half]     + bias[col];
            float v1 = acc[nj][2 * half + 1] + bias[col + 1];
            if (MODE == 0) {
                v0 = 0.5f * v0 * (1.0f + erff(v0 * 0.70710678118654752f));
                v1 = 0.5f * v1 * (1.0f + erff(v1 * 0.70710678118654752f));
                *(__half2*)(g_h1h + (size_t)row * Cc + col) = __floats2half2_rn(v0, v1);
            } else {
                v0 += g_attn[(size_t)row * Cc + col];
                v1 += g_attn[(size_t)row * Cc + col + 1];
                *(float2*)(g_o + (size_t)row * Cc + col) = make_float2(v0, v1);
            }
        }
    }
}

// ---------------- launch ----------------
extern "C" void kernel_launch(void* const* d_in, const int* in_sizes, int n_in,
                              void* d_out, int out_size) {
    const float* x     = (const float*)d_in[0];
    const float* ln1_w = (const float*)d_in[1];
    const float* ln1_b = (const float*)d_in[2];
    const float* WQ    = (const float*)d_in[3];
    const float* WK    = (const float*)d_in[4];
    const float* WV    = (const float*)d_in[5];
    const float* ln2_w = (const float*)d_in[6];
    const float* ln2_b = (const float*)d_in[7];
    const float* W1    = (const float*)d_in[8];
    const float* b1    = (const float*)d_in[9];
    const float* W2    = (const float*)d_in[10];
    const float* b2    = (const float*)d_in[11];
    float* out = (float*)d_out;

    k_tin_ln<<<dim3(Ss / 32, Nb), dim3(32, 8)>>>(x, ln1_w, ln1_b);
    k_cvtw<<<Cc * Cc / 256, 256>>>(W1, W2, WQ, WK, WV);

    k_qkv<<<dim3(Ss / 128, 12, Nb), 256>>>();

    k_stats<<<dim3(Ss / 128, NH, QSPLIT), 256>>>();
    k_stvs<<<NH * Ss / 64, 256>>>();
    k_flash<<<dim3(Ss / 128, NH, KSPLIT), 256>>>();

    k_oln<<<Nb * Ss, 256>>>(ln2_w, ln2_b);
    k_mlp<0><<<dim3(128, 4), 256>>>(b1);
    k_mlp<1><<<dim3(128, 4), 256>>>(b2);

    k_transpose_out<<<dim3(Ss / 32, Cc / 32, Nb), dim3(32, 8)>>>(out);
}

// round 13
// speedup vs baseline: 1.0497x; 1.0219x over previous
#include <cuda_runtime.h>
#include <cuda_fp16.h>
#include <cstdint>
#include <stdint.h>
#include <math.h>

// ---------------- problem constants ----------------
constexpr int Nb = 2;
constexpr int Cc = 256;
constexpr int Ss = 4096;
constexpr int Hh = 4;
constexpr int Dh = 64;
constexpr int NH = Nb * Hh;
constexpr float EPSV = 1e-5f;
constexpr float QSCALE = (1.0f / 64.0f) * 1.4426950408889634f;  // folded into WQ
constexpr int QSPLIT = 4;
constexpr int KSPLIT = 4;

// ---------------- device scratch ----------------
__device__ float  g_r    [Nb * Ss * Cc];
__device__ __half g_normh[Nb * Ss * Cc];
__device__ __half g_Qh   [NH * Ss * Dh];
__device__ __half g_Kh   [NH * Ss * Dh];
__device__ __half g_Vh   [NH * Ss * Dh];   // post-stats: scaled by inv_k
__device__ float  g_stp  [QSPLIT * NH * Ss];
__device__ float  g_po   [KSPLIT * NH * Ss * Dh];
__device__ float  g_attn [Nb * Ss * Cc];
__device__ __half g_uh   [Nb * Ss * Cc];
__device__ __half g_h1h  [Nb * Ss * Cc];
__device__ __half g_W1h  [Cc * Cc];
__device__ __half g_W2h  [Cc * Cc];
__device__ __half g_WQh  [Hh * Cc * Dh];   // pre-scaled by QSCALE
__device__ __half g_WKh  [Hh * Cc * Dh];
__device__ __half g_WVh  [Hh * Cc * Dh];
__device__ float  g_o    [Nb * Ss * Cc];

// ---------------- helpers ----------------
__device__ __forceinline__ unsigned smem_u32(const void* p) {
    return (unsigned)__cvta_generic_to_shared(p);
}
__device__ __forceinline__ void ldmx4(unsigned* r, unsigned a) {
    asm volatile("ldmatrix.sync.aligned.m8n8.x4.shared.b16 {%0,%1,%2,%3},[%4];"
                 : "=r"(r[0]), "=r"(r[1]), "=r"(r[2]), "=r"(r[3]) : "r"(a));
}
__device__ __forceinline__ void ldmx4t(unsigned* r, unsigned a) {
    asm volatile("ldmatrix.sync.aligned.m8n8.x4.trans.shared.b16 {%0,%1,%2,%3},[%4];"
                 : "=r"(r[0]), "=r"(r[1]), "=r"(r[2]), "=r"(r[3]) : "r"(a));
}
__device__ __forceinline__ void mma16816(float* c, const unsigned* a, const unsigned* b) {
    asm volatile(
        "mma.sync.aligned.m16n8k16.row.col.f32.f16.f16.f32 "
        "{%0,%1,%2,%3},{%4,%5,%6,%7},{%8,%9},{%0,%1,%2,%3};"
        : "+f"(c[0]), "+f"(c[1]), "+f"(c[2]), "+f"(c[3])
        : "r"(a[0]), "r"(a[1]), "r"(a[2]), "r"(a[3]), "r"(b[0]), "r"(b[1]));
}
// fp16-accumulator variant: D/C are 2 regs of half2
__device__ __forceinline__ void mma16816h(unsigned* c, const unsigned* a, const unsigned* b) {
    asm volatile(
        "mma.sync.aligned.m16n8k16.row.col.f16.f16.f16.f16 "
        "{%0,%1},{%2,%3,%4,%5},{%6,%7},{%0,%1};"
        : "+r"(c[0]), "+r"(c[1])
        : "r"(a[0]), "r"(a[1]), "r"(a[2]), "r"(a[3]), "r"(b[0]), "r"(b[1]));
}
__device__ __forceinline__ void cpa16(unsigned dst, const void* src) {
    asm volatile("cp.async.ca.shared.global [%0], [%1], 16;" :: "r"(dst), "l"(src));
}
__device__ __forceinline__ void cpa_commit() {
    asm volatile("cp.async.commit_group;");
}
template <int N>
__device__ __forceinline__ void cpa_wait() {
    asm volatile("cp.async.wait_group %0;" :: "n"(N));
}

// ---------------- fused: transpose+LN1 (blockIdx.y<Nb) / weight convert (y==Nb) ----------------
__global__ void k_tin_ln(const float* __restrict__ x,
                         const float* __restrict__ w, const float* __restrict__ b,
                         const float* __restrict__ W1, const float* __restrict__ W2,
                         const float* __restrict__ WQ, const float* __restrict__ WK,
                         const float* __restrict__ WV) {
    if (blockIdx.y == Nb) {
        // weight conversion: 128 blocks x 256 threads x 2 elems, gap-free
        int tid = threadIdx.y * 32 + threadIdx.x;
#pragma unroll
        for (int j = 0; j < 2; j++) {
            int i = blockIdx.x * 512 + tid + j * 256;
            g_W1h[i] = __float2half(W1[i]);
            g_W2h[i] = __float2half(W2[i]);
            g_WQh[i] = __float2half(WQ[i] * QSCALE);
            g_WKh[i] = __float2half(WK[i]);
            g_WVh[i] = __float2half(WV[i]);
        }
        return;
    }
    __shared__ float t[256][33];
    int n = blockIdx.y, s0 = blockIdx.x * 32;
    int tx = threadIdx.x, ty = threadIdx.y;
#pragma unroll
    for (int i = 0; i < 32; i++)
        t[ty + 8 * i][tx] = x[((size_t)(n * Cc + ty + 8 * i)) * Ss + s0 + tx];
    __syncthreads();
    int lane = tx;
#pragma unroll
    for (int j = 0; j < 4; j++) {
        int s = ty * 4 + j;
        float vals[8];
        float s1 = 0.f, s2 = 0.f;
#pragma unroll
        for (int u = 0; u < 8; u++) {
            float v = t[lane + 32 * u][s];
            vals[u] = v; s1 += v; s2 += v * v;
        }
#pragma unroll
        for (int o = 16; o; o >>= 1) {
            s1 += __shfl_xor_sync(0xffffffffu, s1, o);
            s2 += __shfl_xor_sync(0xffffffffu, s2, o);
        }
        float mean = s1 * (1.0f / Cc);
        float rstd = rsqrtf(s2 * (1.0f / Cc) - mean * mean + EPSV);
        size_t rowo = ((size_t)n * Ss + s0 + s) * Cc;
#pragma unroll
        for (int u = 0; u < 8; u++) {
            int c = lane + 32 * u;
            g_r[rowo + c] = vals[u];
            g_normh[rowo + c] = __float2half((vals[u] - mean) * rstd * w[c] + b[c]);
        }
    }
}

// ---------------- transpose out ----------------
__global__ void k_transpose_out(float* __restrict__ out) {
    __shared__ float t[32][33];
    int n = blockIdx.z;
    int s0 = blockIdx.x * 32, c0 = blockIdx.y * 32;
    int tx = threadIdx.x, ty = threadIdx.y;
#pragma unroll
    for (int i = 0; i < 4; i++)
        t[ty + 8 * i][tx] = g_o[((size_t)(n * Ss + s0 + ty + 8 * i)) * Cc + c0 + tx];
    __syncthreads();
#pragma unroll
    for (int i = 0; i < 4; i++)
        out[((size_t)(n * Cc + c0 + ty + 8 * i)) * Ss + s0 + tx] = t[tx][ty + 8 * i];
}

// ---------------- fused: O-combine + residual + LN2 -> g_attn, g_uh ----------------
__global__ void k_oln(const float* __restrict__ w, const float* __restrict__ b) {
    int row = blockIdx.x;
    int t = threadIdx.x;
    int n = row >> 12, q = row & 4095;
    int h = t >> 6, d = t & 63;
    int nh = n * 4 + h;
    float val = 0.f;
#pragma unroll
    for (int ks = 0; ks < KSPLIT; ks++)
        val += g_po[((size_t)(ks * NH + nh) * Ss + q) * Dh + d];
    size_t idx = (size_t)row * Cc + t;
    g_attn[idx] = val;
    float v = val + g_r[idx];

    float s1 = v, s2 = v * v;
#pragma unroll
    for (int o = 16; o; o >>= 1) {
        s1 += __shfl_xor_sync(0xffffffffu, s1, o);
        s2 += __shfl_xor_sync(0xffffffffu, s2, o);
    }
    __shared__ float sm1[8], sm2[8];
    __shared__ float mb, rb;
    int w8 = t >> 5, lane = t & 31;
    if (!lane) { sm1[w8] = s1; sm2[w8] = s2; }
    __syncthreads();
    if (t == 0) {
        float a = 0.f, qq = 0.f;
#pragma unroll
        for (int i = 0; i < 8; i++) { a += sm1[i]; qq += sm2[i]; }
        float mean = a * (1.0f / Cc);
        mb = mean;
        rb = rsqrtf(qq * (1.0f / Cc) - mean * mean + EPSV);
    }
    __syncthreads();
    g_uh[idx] = __float2half((v - mb) * rb * w[t] + b[t]);
}

// ---------------- QKV projection, fp16 mma, pre-converted weights ----------------
__global__ __launch_bounds__(256) void k_qkv() {
    int which = blockIdx.y >> 2;
    int h = blockIdx.y & 3;
    int n = blockIdx.z;
    int m0 = blockIdx.x * 128;
    const __half* W = (which == 0 ? g_WQh : which == 1 ? g_WKh : g_WVh) + h * Cc * Dh;
    __half* Out = (which == 0 ? g_Qh : which == 1 ? g_Kh : g_Vh) + (size_t)(n * 4 + h) * Ss * Dh;
    const __half* A = g_normh + (size_t)n * Ss * Cc;

    __shared__ __half As[128][88];
    __shared__ __half Bs[64][88];
    int tid = threadIdx.x, lane = tid & 31, wid = tid >> 5;
    int wm = (wid >> 1) * 32;
    int wn = (wid & 1) * 32;
    float acc[2][4][4] = {};

    for (int kb = 0; kb < Cc; kb += 64) {
#pragma unroll
        for (int i = 0; i < 4; i++) {
            int idx = tid + i * 256;
            int r = idx >> 3, c8 = idx & 7;
            *(float4*)&As[r][c8 * 8] = *(const float4*)(A + (size_t)(m0 + r) * Cc + kb + c8 * 8);
        }
#pragma unroll
        for (int i = 0; i < 2; i++) {
            int idx = tid + i * 256;
            int r = idx >> 3, c8 = idx & 7;
            *(float4*)&Bs[r][c8 * 8] = *(const float4*)(W + (size_t)(kb + r) * Dh + c8 * 8);
        }
        __syncthreads();
#pragma unroll
        for (int kk = 0; kk < 64; kk += 16) {
            unsigned a[2][4], b[4][2];
#pragma unroll
            for (int mi = 0; mi < 2; mi++)
                ldmx4(a[mi], smem_u32(&As[wm + mi * 16 + (lane & 15)][kk + (lane >> 4) * 8]));
#pragma unroll
            for (int p = 0; p < 2; p++) {
                unsigned r4[4];
                ldmx4t(r4, smem_u32(&Bs[kk + (lane & 7) + ((lane >> 3) & 1) * 8]
                                       [wn + p * 16 + (lane >> 4) * 8]));
                b[2 * p][0] = r4[0]; b[2 * p][1] = r4[1];
                b[2 * p + 1][0] = r4[2]; b[2 * p + 1][1] = r4[3];
            }
#pragma unroll
            for (int mi = 0; mi < 2; mi++)
#pragma unroll
                for (int nj = 0; nj < 4; nj++)
                    mma16816(acc[mi][nj], a[mi], b[nj]);
        }
        __syncthreads();
    }
#pragma unroll
    for (int mi = 0; mi < 2; mi++) {
        int r = m0 + wm + mi * 16 + (lane >> 2);
#pragma unroll
        for (int nj = 0; nj < 4; nj++) {
            int c = wn + nj * 8 + 2 * (lane & 3);
            *(__half2*)(Out + (size_t)r * Dh + c) =
                __floats2half2_rn(acc[mi][nj][0], acc[mi][nj][1]);
            *(__half2*)(Out + (size_t)(r + 8) * Dh + c) =
                __floats2half2_rn(acc[mi][nj][2], acc[mi][nj][3]);
        }
    }
}

// ---------------- pass 1: per-k partial sum of exp2(S); row-sum via tensor core ----------------
__global__ __launch_bounds__(256) void k_stats() {
    int nh = blockIdx.y;
    int qs = blockIdx.z;
    int k0 = blockIdx.x * 128;
    const __half* Kp = g_Kh + (size_t)nh * Ss * Dh;
    const __half* Qp = g_Qh + (size_t)nh * Ss * Dh;
    constexpr int NITER = Ss / 128 / QSPLIT;   // 8
    int qbase = qs * (Ss / QSPLIT);

    __shared__ __half As[128][72];
    __shared__ __half Bs[2][128][72];
    __shared__ float sred[2][128];

    int tid = threadIdx.x, lane = tid & 31, wid = tid >> 5;
    int wm = (wid >> 1) * 32;
    int wn = (wid & 1) * 64;

#pragma unroll
    for (int i = 0; i < 4; i++) {
        int idx = tid + i * 256;
        int r = idx >> 3, c8 = idx & 7;
        *(float4*)&As[r][c8 * 8] = *(const float4*)(Kp + (size_t)(k0 + r) * Dh + c8 * 8);
    }
#pragma unroll
    for (int i = 0; i < 4; i++) {
        int idx = tid + i * 256;
        int r = idx >> 3, c8 = idx & 7;
        cpa16(smem_u32(&Bs[0][r][c8 * 8]), Qp + (size_t)(qbase + r) * Dh + c8 * 8);
    }
    cpa_commit();
    __syncthreads();

    unsigned a[2][4][4];
#pragma unroll
    for (int mi = 0; mi < 2; mi++)
#pragma unroll
        for (int t = 0; t < 4; t++)
            ldmx4(a[mi][t], smem_u32(&As[wm + mi * 16 + (lane & 15)][t * 16 + (lane >> 4) * 8]));

    const unsigned bone[2] = {0x3C003C00u, 0x3C003C00u};   // ones B-fragment
    float rs[2][4] = {};   // fp32 row-sum D-frags per mi

    for (int c = 0; c < NITER; c++) {
        __syncthreads();
        if (c + 1 < NITER) {
            int q1 = qbase + (c + 1) * 128;
            int bufn = (c + 1) & 1;
#pragma unroll
            for (int i = 0; i < 4; i++) {
                int idx = tid + i * 256;
                int r = idx >> 3, c8 = idx & 7;
                cpa16(smem_u32(&Bs[bufn][r][c8 * 8]), Qp + (size_t)(q1 + r) * Dh + c8 * 8);
            }
            cpa_commit();
            cpa_wait<1>();
        } else {
            cpa_wait<0>();
        }
        __syncthreads();
        int buf = c & 1;

        unsigned acc[2][8][2] = {};   // f16x2 S accumulators
#pragma unroll
        for (int t = 0; t < 4; t++) {
            unsigned b[8][2];
#pragma unroll
            for (int p = 0; p < 4; p++) {
                unsigned r4[4];
                ldmx4(r4, smem_u32(&Bs[buf][wn + p * 16 + (lane & 7) + (lane >> 4) * 8]
                                         [t * 16 + ((lane >> 3) & 1) * 8]));
                b[2 * p][0] = r4[0]; b[2 * p][1] = r4[1];
                b[2 * p + 1][0] = r4[2]; b[2 * p + 1][1] = r4[3];
            }
#pragma unroll
            for (int mi = 0; mi < 2; mi++)
#pragma unroll
                for (int nj = 0; nj < 8; nj++)
                    mma16816h(acc[mi][nj], a[mi][t], b[nj]);
        }
        // P = exp2(S) packed as A-frags; row-sum via P @ ones on tensor pipe
#pragma unroll
        for (int mi = 0; mi < 2; mi++)
#pragma unroll
            for (int t = 0; t < 4; t++) {
                unsigned apf[4];
                __half2 e0 = h2exp2(*(__half2*)&acc[mi][2 * t][0]);
                __half2 e1 = h2exp2(*(__half2*)&acc[mi][2 * t][1]);
                __half2 e2 = h2exp2(*(__half2*)&acc[mi][2 * t + 1][0]);
                __half2 e3 = h2exp2(*(__half2*)&acc[mi][2 * t + 1][1]);
                apf[0] = *(unsigned*)&e0;
                apf[1] = *(unsigned*)&e1;
                apf[2] = *(unsigned*)&e2;
                apf[3] = *(unsigned*)&e3;
                mma16816(rs[mi], apf, bone);
            }
    }

    // rs[mi][0] = complete row sum for row wm+mi*16+(lane>>2); rs[mi][2] = row+8
    __syncthreads();
    if ((lane & 3) == 0) {
#pragma unroll
        for (int mi = 0; mi < 2; mi++) {
            int row = wm + mi * 16 + (lane >> 2);
            sred[wid & 1][row]     = rs[mi][0];
            sred[wid & 1][row + 8] = rs[mi][2];
        }
    }
    __syncthreads();
    if (tid < 128)
        g_stp[(qs * NH + nh) * Ss + k0 + tid] = sred[0][tid] + sred[1][tid];
}

// ---------------- combine partial sums + scale V by inv_k (in place) ----------------
__global__ void k_stvs() {
    int base = blockIdx.x * 64;
    __shared__ float sinv[64];
    int tid = threadIdx.x;
    if (tid < 64) {
        int i = base + tid;
        float s = 0.f;
#pragma unroll
        for (int qs = 0; qs < QSPLIT; qs++)
            s += g_stp[qs * NH * Ss + i];
        sinv[tid] = 1.0f / s;
    }
    __syncthreads();
    __half2* V2 = (__half2*)g_Vh;
#pragma unroll
    for (int j = 0; j < 8; j++) {
        int idx = tid + j * 256;
        int row = idx >> 5, c2 = idx & 31;
        float inv = sinv[row];
        size_t o = (size_t)(base + row) * 32 + c2;
        float2 vf = __half22float2(V2[o]);
        V2[o] = __floats2half2_rn(vf.x * inv, vf.y * inv);
    }
}

// ---------------- pass 2: flash attn; f16-acc S, P = exp2(S) in place ----------------
__global__ __launch_bounds__(256, 2) void k_flash() {
    int nh = blockIdx.y;
    int ks = blockIdx.z;
    int q0 = blockIdx.x * 128;
    const __half* Qp = g_Qh + (size_t)nh * Ss * Dh;
    const __half* Kp = g_Kh + (size_t)nh * Ss * Dh;
    const __half* Vp = g_Vh + (size_t)nh * Ss * Dh;
    constexpr int NITER = Ss / 32 / KSPLIT;   // 32
    int kbase = ks * (Ss / KSPLIT);

    __shared__ __half Qs[128][72];
    __shared__ __half Ks[2][32][72];
    __shared__ __half Vs[2][32][72];

    int tid = threadIdx.x, lane = tid & 31, wid = tid >> 5;
    int wm = wid * 16;
    int lr = tid >> 3, lc8 = tid & 7;

#pragma unroll
    for (int i = 0; i < 4; i++) {
        int idx = tid + i * 256;
        int r = idx >> 3, c8 = idx & 7;
        *(float4*)&Qs[r][c8 * 8] = *(const float4*)(Qp + (size_t)(q0 + r) * Dh + c8 * 8);
    }
    cpa16(smem_u32(&Ks[0][lr][lc8 * 8]), Kp + (size_t)(kbase + lr) * Dh + lc8 * 8);
    cpa16(smem_u32(&Vs[0][lr][lc8 * 8]), Vp + (size_t)(kbase + lr) * Dh + lc8 * 8);
    cpa_commit();
    __syncthreads();

    unsigned aq[4][4];
#pragma unroll
    for (int t = 0; t < 4; t++)
        ldmx4(aq[t], smem_u32(&Qs[wm + (lane & 15)][t * 16 + (lane >> 4) * 8]));

    float accO[8][4] = {};

    for (int c = 0; c < NITER; c++) {
        __syncthreads();
        if (c + 1 < NITER) {
            int kb1 = kbase + (c + 1) * 32;
            int bufn = (c + 1) & 1;
            cpa16(smem_u32(&Ks[bufn][lr][lc8 * 8]), Kp + (size_t)(kb1 + lr) * Dh + lc8 * 8);
            cpa16(smem_u32(&Vs[bufn][lr][lc8 * 8]), Vp + (size_t)(kb1 + lr) * Dh + lc8 * 8);
            cpa_commit();
            cpa_wait<1>();
        } else {
            cpa_wait<0>();
        }
        __syncthreads();
        int buf = c & 1;

        unsigned accS[4][2] = {};
#pragma unroll
        for (int t = 0; t < 4; t++) {
            unsigned b[4][2];
#pragma unroll
            for (int p = 0; p < 2; p++) {
                unsigned r4[4];
                ldmx4(r4, smem_u32(&Ks[buf][p * 16 + (lane & 7) + (lane >> 4) * 8]
                                         [t * 16 + ((lane >> 3) & 1) * 8]));
                b[2 * p][0] = r4[0]; b[2 * p][1] = r4[1];
                b[2 * p + 1][0] = r4[2]; b[2 * p + 1][1] = r4[3];
            }
#pragma unroll
            for (int nj = 0; nj < 4; nj++)
                mma16816h(accS[nj], aq[t], b[nj]);
        }

        unsigned ap[2][4];
#pragma unroll
        for (int nj = 0; nj < 4; nj++) {
            __half2 e0 = h2exp2(*(__half2*)&accS[nj][0]);
            __half2 e1 = h2exp2(*(__half2*)&accS[nj][1]);
            int t = nj >> 1, w2 = (nj & 1) * 2;
            ap[t][w2]     = *(unsigned*)&e0;
            ap[t][w2 + 1] = *(unsigned*)&e1;
        }

#pragma unroll
        for (int t = 0; t < 2; t++) {
            unsigned bv[8][2];
#pragma unroll
            for (int p = 0; p < 4; p++) {
                unsigned r4[4];
                ldmx4t(r4, smem_u32(&Vs[buf][t * 16 + (lane & 7) + ((lane >> 3) & 1) * 8]
                                          [p * 16 + (lane >> 4) * 8]));
                bv[2 * p][0] = r4[0]; bv[2 * p][1] = r4[1];
                bv[2 * p + 1][0] = r4[2]; bv[2 * p + 1][1] = r4[3];
            }
#pragma unroll
            for (int dj = 0; dj < 8; dj++)
                mma16816(accO[dj], ap[t], bv[dj]);
        }
    }

    float* Po = g_po + ((size_t)(ks * NH + nh) * Ss) * Dh;
#pragma unroll
    for (int dj = 0; dj < 8; dj++) {
        int q = q0 + wm + (lane >> 2);
        int col = dj * 8 + 2 * (lane & 3);
        *(float2*)(Po + (size_t)q * Dh + col) = make_float2(accO[dj][0], accO[dj][1]);
        *(float2*)(Po + (size_t)(q + 8) * Dh + col) = make_float2(accO[dj][2], accO[dj][3]);
    }
}

// ---------------- MLP GEMMs, fp16 mma, 64x64 blocks ----------------
template <int MODE>
__global__ __launch_bounds__(256) void k_mlp(const float* __restrict__ bias) {
    int m0 = blockIdx.x * 64;
    int n0 = blockIdx.y * 64;
    const __half* A = (MODE == 0) ? g_uh : g_h1h;
    const __half* W = (MODE == 0) ? g_W1h : g_W2h;

    __shared__ __half As[64][88];
    __shared__ __half Bs[64][88];
    int tid = threadIdx.x, lane = tid & 31, wid = tid >> 5;
    int wm = (wid >> 1) * 16;
    int wn = (wid & 1) * 32;
    float acc[4][4] = {};

    for (int kb = 0; kb < Cc; kb += 64) {
#pragma unroll
        for (int i = 0; i < 2; i++) {
            int idx = tid + i * 256;
            int r = idx >> 3, c8 = idx & 7;
            *(float4*)&As[r][c8 * 8] = *(const float4*)(A + (size_t)(m0 + r) * Cc + kb + c8 * 8);
            *(float4*)&Bs[r][c8 * 8] = *(const float4*)(W + (size_t)(kb + r) * Cc + n0 + c8 * 8);
        }
        __syncthreads();
#pragma unroll
        for (int kk = 0; kk < 64; kk += 16) {
            unsigned a[4], b[4][2];
            ldmx4(a, smem_u32(&As[wm + (lane & 15)][kk + (lane >> 4) * 8]));
#pragma unroll
            for (int p = 0; p < 2; p++) {
                unsigned r4[4];
                ldmx4t(r4, smem_u32(&Bs[kk + (lane & 7) + ((lane >> 3) & 1) * 8]
                                       [wn + p * 16 + (lane >> 4) * 8]));
                b[2 * p][0] = r4[0]; b[2 * p][1] = r4[1];
                b[2 * p + 1][0] = r4[2]; b[2 * p + 1][1] = r4[3];
            }
#pragma unroll
            for (int nj = 0; nj < 4; nj++)
                mma16816(acc[nj], a, b[nj]);
        }
        __syncthreads();
    }
#pragma unroll
    for (int half = 0; half < 2; half++) {
        int row = m0 + wm + half * 8 + (lane >> 2);
#pragma unroll
        for (int nj = 0; nj < 4; nj++) {
            int col = n0 + wn + nj * 8 + 2 * (lane & 3);
            float v0 = acc[nj][2 * half]     + bias[col];
            float v1 = acc[nj][2 * half + 1] + bias[col + 1];
            if (MODE == 0) {
                v0 = 0.5f * v0 * (1.0f + erff(v0 * 0.70710678118654752f));
                v1 = 0.5f * v1 * (1.0f + erff(v1 * 0.70710678118654752f));
                *(__half2*)(g_h1h + (size_t)row * Cc + col) = __floats2half2_rn(v0, v1);
            } else {
                v0 += g_attn[(size_t)row * Cc + col];
                v1 += g_attn[(size_t)row * Cc + col + 1];
                *(float2*)(g_o + (size_t)row * Cc + col) = make_float2(v0, v1);
            }
        }
    }
}

// ---------------- launch ----------------
extern "C" void kernel_launch(void* const* d_in, const int* in_sizes, int n_in,
                              void* d_out, int out_size) {
    const float* x     = (const float*)d_in[0];
    const float* ln1_w = (const float*)d_in[1];
    const float* ln1_b = (const float*)d_in[2];
    const float* WQ    = (const float*)d_in[3];
    const float* WK    = (const float*)d_in[4];
    const float* WV    = (const float*)d_in[5];
    const float* ln2_w = (const float*)d_in[6];
    const float* ln2_b = (const float*)d_in[7];
    const float* W1    = (const float*)d_in[8];
    const float* b1    = (const float*)d_in[9];
    const float* W2    = (const float*)d_in[10];
    const float* b2    = (const float*)d_in[11];
    float* out = (float*)d_out;

    k_tin_ln<<<dim3(Ss / 32, Nb + 1), dim3(32, 8)>>>(x, ln1_w, ln1_b, W1, W2, WQ, WK, WV);

    k_qkv<<<dim3(Ss / 128, 12, Nb), 256>>>();

    k_stats<<<dim3(Ss / 128, NH, QSPLIT), 256>>>();
    k_stvs<<<NH * Ss / 64, 256>>>();
    k_flash<<<dim3(Ss / 128, NH, KSPLIT), 256>>>();

    k_oln<<<Nb * Ss, 256>>>(ln2_w, ln2_b);
    k_mlp<0><<<dim3(128, 4), 256>>>(b1);
    k_mlp<1><<<dim3(128, 4), 256>>>(b2);

    k_transpose_out<<<dim3(Ss / 32, Cc / 32, Nb), dim3(32, 8)>>>(out);
}

// round 14
// speedup vs baseline: 1.0704x; 1.0197x over previous
#include <cuda_runtime.h>
#include <cuda_fp16.h>
#include <cstdint>
#include <stdint.h>
#include <math.h>

// ---------------- problem constants ----------------
constexpr int Nb = 2;
constexpr int Cc = 256;
constexpr int Ss = 4096;
constexpr int Hh = 4;
constexpr int Dh = 64;
constexpr int NH = Nb * Hh;
constexpr float EPSV = 1e-5f;
constexpr float QSCALE = (1.0f / 64.0f) * 1.4426950408889634f;  // folded into WQ
constexpr int QSPLIT = 4;
constexpr int KSPLIT = 4;

// ---------------- device scratch ----------------
__device__ float  g_r    [Nb * Ss * Cc];
__device__ __half g_normh[Nb * Ss * Cc];
__device__ __half g_Qh   [NH * Ss * Dh];
__device__ __half g_Kh   [NH * Ss * Dh];
__device__ __half g_Vh   [NH * Ss * Dh];   // post-stats: scaled by inv_k
__device__ float  g_stp  [QSPLIT * NH * Ss];
__device__ float  g_po   [KSPLIT * NH * Ss * Dh];
__device__ float  g_attn [Nb * Ss * Cc];
__device__ __half g_uh   [Nb * Ss * Cc];
__device__ __half g_h1h  [Nb * Ss * Cc];
__device__ __half g_W1h  [Cc * Cc];
__device__ __half g_W2h  [Cc * Cc];
__device__ __half g_WQh  [Hh * Cc * Dh];   // pre-scaled by QSCALE
__device__ __half g_WKh  [Hh * Cc * Dh];
__device__ __half g_WVh  [Hh * Cc * Dh];

// ---------------- helpers ----------------
__device__ __forceinline__ unsigned smem_u32(const void* p) {
    return (unsigned)__cvta_generic_to_shared(p);
}
__device__ __forceinline__ void ldmx4(unsigned* r, unsigned a) {
    asm volatile("ldmatrix.sync.aligned.m8n8.x4.shared.b16 {%0,%1,%2,%3},[%4];"
                 : "=r"(r[0]), "=r"(r[1]), "=r"(r[2]), "=r"(r[3]) : "r"(a));
}
__device__ __forceinline__ void ldmx4t(unsigned* r, unsigned a) {
    asm volatile("ldmatrix.sync.aligned.m8n8.x4.trans.shared.b16 {%0,%1,%2,%3},[%4];"
                 : "=r"(r[0]), "=r"(r[1]), "=r"(r[2]), "=r"(r[3]) : "r"(a));
}
__device__ __forceinline__ void mma16816(float* c, const unsigned* a, const unsigned* b) {
    asm volatile(
        "mma.sync.aligned.m16n8k16.row.col.f32.f16.f16.f32 "
        "{%0,%1,%2,%3},{%4,%5,%6,%7},{%8,%9},{%0,%1,%2,%3};"
        : "+f"(c[0]), "+f"(c[1]), "+f"(c[2]), "+f"(c[3])
        : "r"(a[0]), "r"(a[1]), "r"(a[2]), "r"(a[3]), "r"(b[0]), "r"(b[1]));
}
// fp16-accumulator variant: D/C are 2 regs of half2
__device__ __forceinline__ void mma16816h(unsigned* c, const unsigned* a, const unsigned* b) {
    asm volatile(
        "mma.sync.aligned.m16n8k16.row.col.f16.f16.f16.f16 "
        "{%0,%1},{%2,%3,%4,%5},{%6,%7},{%0,%1};"
        : "+r"(c[0]), "+r"(c[1])
        : "r"(a[0]), "r"(a[1]), "r"(a[2]), "r"(a[3]), "r"(b[0]), "r"(b[1]));
}
__device__ __forceinline__ void cpa16(unsigned dst, const void* src) {
    asm volatile("cp.async.ca.shared.global [%0], [%1], 16;" :: "r"(dst), "l"(src));
}
__device__ __forceinline__ void cpa_commit() {
    asm volatile("cp.async.commit_group;");
}
template <int N>
__device__ __forceinline__ void cpa_wait() {
    asm volatile("cp.async.wait_group %0;" :: "n"(N));
}

// ---------------- fused: transpose+LN1 (blockIdx.y<Nb) / weight convert (y==Nb) ----------------
__global__ void k_tin_ln(const float* __restrict__ x,
                         const float* __restrict__ w, const float* __restrict__ b,
                         const float* __restrict__ W1, const float* __restrict__ W2,
                         const float* __restrict__ WQ, const float* __restrict__ WK,
                         const float* __restrict__ WV) {
    if (blockIdx.y == Nb) {
        int tid = threadIdx.y * 32 + threadIdx.x;
#pragma unroll
        for (int j = 0; j < 2; j++) {
            int i = blockIdx.x * 512 + tid + j * 256;
            g_W1h[i] = __float2half(W1[i]);
            g_W2h[i] = __float2half(W2[i]);
            g_WQh[i] = __float2half(WQ[i] * QSCALE);
            g_WKh[i] = __float2half(WK[i]);
            g_WVh[i] = __float2half(WV[i]);
        }
        return;
    }
    __shared__ float t[256][33];
    int n = blockIdx.y, s0 = blockIdx.x * 32;
    int tx = threadIdx.x, ty = threadIdx.y;
#pragma unroll
    for (int i = 0; i < 32; i++)
        t[ty + 8 * i][tx] = x[((size_t)(n * Cc + ty + 8 * i)) * Ss + s0 + tx];
    __syncthreads();
    int lane = tx;
#pragma unroll
    for (int j = 0; j < 4; j++) {
        int s = ty * 4 + j;
        float vals[8];
        float s1 = 0.f, s2 = 0.f;
#pragma unroll
        for (int u = 0; u < 8; u++) {
            float v = t[lane + 32 * u][s];
            vals[u] = v; s1 += v; s2 += v * v;
        }
#pragma unroll
        for (int o = 16; o; o >>= 1) {
            s1 += __shfl_xor_sync(0xffffffffu, s1, o);
            s2 += __shfl_xor_sync(0xffffffffu, s2, o);
        }
        float mean = s1 * (1.0f / Cc);
        float rstd = rsqrtf(s2 * (1.0f / Cc) - mean * mean + EPSV);
        size_t rowo = ((size_t)n * Ss + s0 + s) * Cc;
#pragma unroll
        for (int u = 0; u < 8; u++) {
            int c = lane + 32 * u;
            g_r[rowo + c] = vals[u];
            g_normh[rowo + c] = __float2half((vals[u] - mean) * rstd * w[c] + b[c]);
        }
    }
}

// ---------------- fused: O-combine + residual + LN2 -> g_attn, g_uh ----------------
__global__ void k_oln(const float* __restrict__ w, const float* __restrict__ b) {
    int row = blockIdx.x;
    int t = threadIdx.x;
    int n = row >> 12, q = row & 4095;
    int h = t >> 6, d = t & 63;
    int nh = n * 4 + h;
    float val = 0.f;
#pragma unroll
    for (int ks = 0; ks < KSPLIT; ks++)
        val += g_po[((size_t)(ks * NH + nh) * Ss + q) * Dh + d];
    size_t idx = (size_t)row * Cc + t;
    g_attn[idx] = val;
    float v = val + g_r[idx];

    float s1 = v, s2 = v * v;
#pragma unroll
    for (int o = 16; o; o >>= 1) {
        s1 += __shfl_xor_sync(0xffffffffu, s1, o);
        s2 += __shfl_xor_sync(0xffffffffu, s2, o);
    }
    __shared__ float sm1[8], sm2[8];
    __shared__ float mb, rb;
    int w8 = t >> 5, lane = t & 31;
    if (!lane) { sm1[w8] = s1; sm2[w8] = s2; }
    __syncthreads();
    if (t == 0) {
        float a = 0.f, qq = 0.f;
#pragma unroll
        for (int i = 0; i < 8; i++) { a += sm1[i]; qq += sm2[i]; }
        float mean = a * (1.0f / Cc);
        mb = mean;
        rb = rsqrtf(qq * (1.0f / Cc) - mean * mean + EPSV);
    }
    __syncthreads();
    g_uh[idx] = __float2half((v - mb) * rb * w[t] + b[t]);
}

// ---------------- QKV projection, fp16 mma, pre-converted weights ----------------
__global__ __launch_bounds__(256) void k_qkv() {
    int which = blockIdx.y >> 2;
    int h = blockIdx.y & 3;
    int n = blockIdx.z;
    int m0 = blockIdx.x * 128;
    const __half* W = (which == 0 ? g_WQh : which == 1 ? g_WKh : g_WVh) + h * Cc * Dh;
    __half* Out = (which == 0 ? g_Qh : which == 1 ? g_Kh : g_Vh) + (size_t)(n * 4 + h) * Ss * Dh;
    const __half* A = g_normh + (size_t)n * Ss * Cc;

    __shared__ __half As[128][88];
    __shared__ __half Bs[64][88];
    int tid = threadIdx.x, lane = tid & 31, wid = tid >> 5;
    int wm = (wid >> 1) * 32;
    int wn = (wid & 1) * 32;
    float acc[2][4][4] = {};

    for (int kb = 0; kb < Cc; kb += 64) {
#pragma unroll
        for (int i = 0; i < 4; i++) {
            int idx = tid + i * 256;
            int r = idx >> 3, c8 = idx & 7;
            *(float4*)&As[r][c8 * 8] = *(const float4*)(A + (size_t)(m0 + r) * Cc + kb + c8 * 8);
        }
#pragma unroll
        for (int i = 0; i < 2; i++) {
            int idx = tid + i * 256;
            int r = idx >> 3, c8 = idx & 7;
            *(float4*)&Bs[r][c8 * 8] = *(const float4*)(W + (size_t)(kb + r) * Dh + c8 * 8);
        }
        __syncthreads();
#pragma unroll
        for (int kk = 0; kk < 64; kk += 16) {
            unsigned a[2][4], b[4][2];
#pragma unroll
            for (int mi = 0; mi < 2; mi++)
                ldmx4(a[mi], smem_u32(&As[wm + mi * 16 + (lane & 15)][kk + (lane >> 4) * 8]));
#pragma unroll
            for (int p = 0; p < 2; p++) {
                unsigned r4[4];
                ldmx4t(r4, smem_u32(&Bs[kk + (lane & 7) + ((lane >> 3) & 1) * 8]
                                       [wn + p * 16 + (lane >> 4) * 8]));
                b[2 * p][0] = r4[0]; b[2 * p][1] = r4[1];
                b[2 * p + 1][0] = r4[2]; b[2 * p + 1][1] = r4[3];
            }
#pragma unroll
            for (int mi = 0; mi < 2; mi++)
#pragma unroll
                for (int nj = 0; nj < 4; nj++)
                    mma16816(acc[mi][nj], a[mi], b[nj]);
        }
        __syncthreads();
    }
#pragma unroll
    for (int mi = 0; mi < 2; mi++) {
        int r = m0 + wm + mi * 16 + (lane >> 2);
#pragma unroll
        for (int nj = 0; nj < 4; nj++) {
            int c = wn + nj * 8 + 2 * (lane & 3);
            *(__half2*)(Out + (size_t)r * Dh + c) =
                __floats2half2_rn(acc[mi][nj][0], acc[mi][nj][1]);
            *(__half2*)(Out + (size_t)(r + 8) * Dh + c) =
                __floats2half2_rn(acc[mi][nj][2], acc[mi][nj][3]);
        }
    }
}

// ---------------- pass 1: per-k partial sum of exp2(S); row-sum via tensor core ----------------
__global__ __launch_bounds__(256) void k_stats() {
    int nh = blockIdx.y;
    int qs = blockIdx.z;
    int k0 = blockIdx.x * 128;
    const __half* Kp = g_Kh + (size_t)nh * Ss * Dh;
    const __half* Qp = g_Qh + (size_t)nh * Ss * Dh;
    constexpr int NITER = Ss / 128 / QSPLIT;   // 8
    int qbase = qs * (Ss / QSPLIT);

    __shared__ __half As[128][72];
    __shared__ __half Bs[2][128][72];
    __shared__ float sred[2][128];

    int tid = threadIdx.x, lane = tid & 31, wid = tid >> 5;
    int wm = (wid >> 1) * 32;
    int wn = (wid & 1) * 64;

#pragma unroll
    for (int i = 0; i < 4; i++) {
        int idx = tid + i * 256;
        int r = idx >> 3, c8 = idx & 7;
        *(float4*)&As[r][c8 * 8] = *(const float4*)(Kp + (size_t)(k0 + r) * Dh + c8 * 8);
    }
#pragma unroll
    for (int i = 0; i < 4; i++) {
        int idx = tid + i * 256;
        int r = idx >> 3, c8 = idx & 7;
        cpa16(smem_u32(&Bs[0][r][c8 * 8]), Qp + (size_t)(qbase + r) * Dh + c8 * 8);
    }
    cpa_commit();
    __syncthreads();

    unsigned a[2][4][4];
#pragma unroll
    for (int mi = 0; mi < 2; mi++)
#pragma unroll
        for (int t = 0; t < 4; t++)
            ldmx4(a[mi][t], smem_u32(&As[wm + mi * 16 + (lane & 15)][t * 16 + (lane >> 4) * 8]));

    const unsigned bone[2] = {0x3C003C00u, 0x3C003C00u};
    float rs[2][4] = {};

    for (int c = 0; c < NITER; c++) {
        __syncthreads();
        if (c + 1 < NITER) {
            int q1 = qbase + (c + 1) * 128;
            int bufn = (c + 1) & 1;
#pragma unroll
            for (int i = 0; i < 4; i++) {
                int idx = tid + i * 256;
                int r = idx >> 3, c8 = idx & 7;
                cpa16(smem_u32(&Bs[bufn][r][c8 * 8]), Qp + (size_t)(q1 + r) * Dh + c8 * 8);
            }
            cpa_commit();
            cpa_wait<1>();
        } else {
            cpa_wait<0>();
        }
        __syncthreads();
        int buf = c & 1;

        unsigned acc[2][8][2] = {};
#pragma unroll
        for (int t = 0; t < 4; t++) {
            unsigned b[8][2];
#pragma unroll
            for (int p = 0; p < 4; p++) {
                unsigned r4[4];
                ldmx4(r4, smem_u32(&Bs[buf][wn + p * 16 + (lane & 7) + (lane >> 4) * 8]
                                         [t * 16 + ((lane >> 3) & 1) * 8]));
                b[2 * p][0] = r4[0]; b[2 * p][1] = r4[1];
                b[2 * p + 1][0] = r4[2]; b[2 * p + 1][1] = r4[3];
            }
#pragma unroll
            for (int mi = 0; mi < 2; mi++)
#pragma unroll
                for (int nj = 0; nj < 8; nj++)
                    mma16816h(acc[mi][nj], a[mi][t], b[nj]);
        }
#pragma unroll
        for (int mi = 0; mi < 2; mi++)
#pragma unroll
            for (int t = 0; t < 4; t++) {
                unsigned apf[4];
                __half2 e0 = h2exp2(*(__half2*)&acc[mi][2 * t][0]);
                __half2 e1 = h2exp2(*(__half2*)&acc[mi][2 * t][1]);
                __half2 e2 = h2exp2(*(__half2*)&acc[mi][2 * t + 1][0]);
                __half2 e3 = h2exp2(*(__half2*)&acc[mi][2 * t + 1][1]);
                apf[0] = *(unsigned*)&e0;
                apf[1] = *(unsigned*)&e1;
                apf[2] = *(unsigned*)&e2;
                apf[3] = *(unsigned*)&e3;
                mma16816(rs[mi], apf, bone);
            }
    }

    __syncthreads();
    if ((lane & 3) == 0) {
#pragma unroll
        for (int mi = 0; mi < 2; mi++) {
            int row = wm + mi * 16 + (lane >> 2);
            sred[wid & 1][row]     = rs[mi][0];
            sred[wid & 1][row + 8] = rs[mi][2];
        }
    }
    __syncthreads();
    if (tid < 128)
        g_stp[(qs * NH + nh) * Ss + k0 + tid] = sred[0][tid] + sred[1][tid];
}

// ---------------- combine partial sums + scale V by inv_k (16 rows/block) ----------------
__global__ void k_stvs() {
    int base = blockIdx.x * 16;
    __shared__ float sinv[16];
    int tid = threadIdx.x;
    if (tid < 16) {
        int i = base + tid;
        float s = 0.f;
#pragma unroll
        for (int qs = 0; qs < QSPLIT; qs++)
            s += g_stp[qs * NH * Ss + i];
        sinv[tid] = 1.0f / s;
    }
    __syncthreads();
    __half2* V2 = (__half2*)g_Vh;
#pragma unroll
    for (int j = 0; j < 2; j++) {
        int idx = tid + j * 256;        // 0..511 = 16 rows x 32 half2
        int row = idx >> 5, c2 = idx & 31;
        float inv = sinv[row];
        size_t o = (size_t)(base + row) * 32 + c2;
        float2 vf = __half22float2(V2[o]);
        V2[o] = __floats2half2_rn(vf.x * inv, vf.y * inv);
    }
}

// ---------------- pass 2: flash attn; f16-acc S, P = exp2(S) in place ----------------
__global__ __launch_bounds__(256, 2) void k_flash() {
    int nh = blockIdx.y;
    int ks = blockIdx.z;
    int q0 = blockIdx.x * 128;
    const __half* Qp = g_Qh + (size_t)nh * Ss * Dh;
    const __half* Kp = g_Kh + (size_t)nh * Ss * Dh;
    const __half* Vp = g_Vh + (size_t)nh * Ss * Dh;
    constexpr int NITER = Ss / 32 / KSPLIT;   // 32
    int kbase = ks * (Ss / KSPLIT);

    __shared__ __half Qs[128][72];
    __shared__ __half Ks[2][32][72];
    __shared__ __half Vs[2][32][72];

    int tid = threadIdx.x, lane = tid & 31, wid = tid >> 5;
    int wm = wid * 16;
    int lr = tid >> 3, lc8 = tid & 7;

#pragma unroll
    for (int i = 0; i < 4; i++) {
        int idx = tid + i * 256;
        int r = idx >> 3, c8 = idx & 7;
        *(float4*)&Qs[r][c8 * 8] = *(const float4*)(Qp + (size_t)(q0 + r) * Dh + c8 * 8);
    }
    cpa16(smem_u32(&Ks[0][lr][lc8 * 8]), Kp + (size_t)(kbase + lr) * Dh + lc8 * 8);
    cpa16(smem_u32(&Vs[0][lr][lc8 * 8]), Vp + (size_t)(kbase + lr) * Dh + lc8 * 8);
    cpa_commit();
    __syncthreads();

    unsigned aq[4][4];
#pragma unroll
    for (int t = 0; t < 4; t++)
        ldmx4(aq[t], smem_u32(&Qs[wm + (lane & 15)][t * 16 + (lane >> 4) * 8]));

    float accO[8][4] = {};

    for (int c = 0; c < NITER; c++) {
        __syncthreads();
        if (c + 1 < NITER) {
            int kb1 = kbase + (c + 1) * 32;
            int bufn = (c + 1) & 1;
            cpa16(smem_u32(&Ks[bufn][lr][lc8 * 8]), Kp + (size_t)(kb1 + lr) * Dh + lc8 * 8);
            cpa16(smem_u32(&Vs[bufn][lr][lc8 * 8]), Vp + (size_t)(kb1 + lr) * Dh + lc8 * 8);
            cpa_commit();
            cpa_wait<1>();
        } else {
            cpa_wait<0>();
        }
        __syncthreads();
        int buf = c & 1;

        unsigned accS[4][2] = {};
#pragma unroll
        for (int t = 0; t < 4; t++) {
            unsigned b[4][2];
#pragma unroll
            for (int p = 0; p < 2; p++) {
                unsigned r4[4];
                ldmx4(r4, smem_u32(&Ks[buf][p * 16 + (lane & 7) + (lane >> 4) * 8]
                                         [t * 16 + ((lane >> 3) & 1) * 8]));
                b[2 * p][0] = r4[0]; b[2 * p][1] = r4[1];
                b[2 * p + 1][0] = r4[2]; b[2 * p + 1][1] = r4[3];
            }
#pragma unroll
            for (int nj = 0; nj < 4; nj++)
                mma16816h(accS[nj], aq[t], b[nj]);
        }

        unsigned ap[2][4];
#pragma unroll
        for (int nj = 0; nj < 4; nj++) {
            __half2 e0 = h2exp2(*(__half2*)&accS[nj][0]);
            __half2 e1 = h2exp2(*(__half2*)&accS[nj][1]);
            int t = nj >> 1, w2 = (nj & 1) * 2;
            ap[t][w2]     = *(unsigned*)&e0;
            ap[t][w2 + 1] = *(unsigned*)&e1;
        }

#pragma unroll
        for (int t = 0; t < 2; t++) {
            unsigned bv[8][2];
#pragma unroll
            for (int p = 0; p < 4; p++) {
                unsigned r4[4];
                ldmx4t(r4, smem_u32(&Vs[buf][t * 16 + (lane & 7) + ((lane >> 3) & 1) * 8]
                                          [p * 16 + (lane >> 4) * 8]));
                bv[2 * p][0] = r4[0]; bv[2 * p][1] = r4[1];
                bv[2 * p + 1][0] = r4[2]; bv[2 * p + 1][1] = r4[3];
            }
#pragma unroll
            for (int dj = 0; dj < 8; dj++)
                mma16816(accO[dj], ap[t], bv[dj]);
        }
    }

    float* Po = g_po + ((size_t)(ks * NH + nh) * Ss) * Dh;
#pragma unroll
    for (int dj = 0; dj < 8; dj++) {
        int q = q0 + wm + (lane >> 2);
        int col = dj * 8 + 2 * (lane & 3);
        *(float2*)(Po + (size_t)q * Dh + col) = make_float2(accO[dj][0], accO[dj][1]);
        *(float2*)(Po + (size_t)(q + 8) * Dh + col) = make_float2(accO[dj][2], accO[dj][3]);
    }
}

// ---------------- MLP GEMMs, fp16 mma, 64x64 blocks ----------------
// MODE 0: g_h1h = half(gelu(uh @ W1h + b1))
// MODE 1: out[n,c,s] = (h1h @ W2h + b2 + g_attn) transposed in-block
template <int MODE>
__global__ __launch_bounds__(256) void k_mlp(const float* __restrict__ bias,
                                             float* __restrict__ out) {
    int m0 = blockIdx.x * 64;
    int n0 = blockIdx.y * 64;
    const __half* A = (MODE == 0) ? g_uh : g_h1h;
    const __half* W = (MODE == 0) ? g_W1h : g_W2h;

    __shared__ __half As[64][88];
    __shared__ __half Bs[64][88];
    __shared__ float Ts[64][65];   // MODE 1 transpose staging
    int tid = threadIdx.x, lane = tid & 31, wid = tid >> 5;
    int wm = (wid >> 1) * 16;
    int wn = (wid & 1) * 32;
    float acc[4][4] = {};

    for (int kb = 0; kb < Cc; kb += 64) {
#pragma unroll
        for (int i = 0; i < 2; i++) {
            int idx = tid + i * 256;
            int r = idx >> 3, c8 = idx & 7;
            *(float4*)&As[r][c8 * 8] = *(const float4*)(A + (size_t)(m0 + r) * Cc + kb + c8 * 8);
            *(float4*)&Bs[r][c8 * 8] = *(const float4*)(W + (size_t)(kb + r) * Cc + n0 + c8 * 8);
        }
        __syncthreads();
#pragma unroll
        for (int kk = 0; kk < 64; kk += 16) {
            unsigned a[4], b[4][2];
            ldmx4(a, smem_u32(&As[wm + (lane & 15)][kk + (lane >> 4) * 8]));
#pragma unroll
            for (int p = 0; p < 2; p++) {
                unsigned r4[4];
                ldmx4t(r4, smem_u32(&Bs[kk + (lane & 7) + ((lane >> 3) & 1) * 8]
                                       [wn + p * 16 + (lane >> 4) * 8]));
                b[2 * p][0] = r4[0]; b[2 * p][1] = r4[1];
                b[2 * p + 1][0] = r4[2]; b[2 * p + 1][1] = r4[3];
            }
#pragma unroll
            for (int nj = 0; nj < 4; nj++)
                mma16816(acc[nj], a, b[nj]);
        }
        __syncthreads();
    }
#pragma unroll
    for (int half = 0; half < 2; half++) {
        int rl = wm + half * 8 + (lane >> 2);     // local row 0..63
        int row = m0 + rl;
#pragma unroll
        for (int nj = 0; nj < 4; nj++) {
            int cl = wn + nj * 8 + 2 * (lane & 3);   // local col 0..63
            int col = n0 + cl;
            float v0 = acc[nj][2 * half]     + bias[col];
            float v1 = acc[nj][2 * half + 1] + bias[col + 1];
            if (MODE == 0) {
                v0 = 0.5f * v0 * (1.0f + erff(v0 * 0.70710678118654752f));
                v1 = 0.5f * v1 * (1.0f + erff(v1 * 0.70710678118654752f));
                *(__half2*)(g_h1h + (size_t)row * Cc + col) = __floats2half2_rn(v0, v1);
            } else {
                v0 += g_attn[(size_t)row * Cc + col];
                v1 += g_attn[(size_t)row * Cc + col + 1];
                Ts[rl][cl] = v0;
                Ts[rl][cl + 1] = v1;
            }
        }
    }
    if (MODE == 1) {
        __syncthreads();
        int n = m0 >> 12, s0 = m0 & 4095;
#pragma unroll
        for (int i = 0; i < 16; i++) {
            int idx = tid + i * 256;
            int cc2 = idx >> 6, ss2 = idx & 63;
            out[((size_t)(n * Cc + n0 + cc2)) * Ss + s0 + ss2] = Ts[ss2][cc2];
        }
    }
}

// ---------------- launch ----------------
extern "C" void kernel_launch(void* const* d_in, const int* in_sizes, int n_in,
                              void* d_out, int out_size) {
    const float* x     = (const float*)d_in[0];
    const float* ln1_w = (const float*)d_in[1];
    const float* ln1_b = (const float*)d_in[2];
    const float* WQ    = (const float*)d_in[3];
    const float* WK    = (const float*)d_in[4];
    const float* WV    = (const float*)d_in[5];
    const float* ln2_w = (const float*)d_in[6];
    const float* ln2_b = (const float*)d_in[7];
    const float* W1    = (const float*)d_in[8];
    const float* b1    = (const float*)d_in[9];
    const float* W2    = (const float*)d_in[10];
    const float* b2    = (const float*)d_in[11];
    float* out = (float*)d_out;

    k_tin_ln<<<dim3(Ss / 32, Nb + 1), dim3(32, 8)>>>(x, ln1_w, ln1_b, W1, W2, WQ, WK, WV);

    k_qkv<<<dim3(Ss / 128, 12, Nb), 256>>>();

    k_stats<<<dim3(Ss / 128, NH, QSPLIT), 256>>>();
    k_stvs<<<NH * Ss / 16, 256>>>();
    k_flash<<<dim3(Ss / 128, NH, KSPLIT), 256>>>();

    k_oln<<<Nb * Ss, 256>>>(ln2_w, ln2_b);
    k_mlp<0><<<dim3(128, 4), 256>>>(b1, nullptr);
    k_mlp<1><<<dim3(128, 4), 256>>>(b2, out);
}